// round 12
// baseline (speedup 1.0000x reference)
#include <cuda_runtime.h>
#include <cuda_bf16.h>
#include <math.h>
#include <stdint.h>

#define N_NODES 100000
#define N_EDGES 600000
#define D       128
#define OUTC    10
#define NLAY    5
#define N_GRAPHS 200
#define SCAN_BLKS 196   // ceil(100000/512)

// ---------------- device scratch (no allocations allowed) ----------------
// ping-pong activation buffers (pre-BN values)
__device__ __align__(128) float g_A[(size_t)N_NODES * D];
__device__ __align__(128) float g_H[(size_t)N_NODES * D];
__device__ __align__(128) __nv_bfloat16 g_Abf[(size_t)N_NODES * D];  // bf16 sidecar of GEMM input
__device__ int   g_deg_out[N_NODES];
__device__ int   g_deg_in[N_NODES];
__device__ float g_norm_out[N_NODES];
__device__ float g_norm_in[N_NODES];
__device__ int   g_row_ptr[N_NODES + 1];
__device__ int   g_cursor[N_NODES];
__device__ int   g_csr_src[N_EDGES];
__device__ int   g_partials[256];
__device__ __nv_bfloat16 g_Bh[NLAY * D * D];   // W transposed [l][n][k], bf16
__device__ float g_pooled[(NLAY + 1) * N_GRAPHS * D];
__device__ float g_bn_sum[NLAY * D];
__device__ float g_bn_sq[NLAY * D];
__device__ float g_bn_a[NLAY * D];
__device__ float g_bn_c[NLAY * D];

__device__ __forceinline__ uint32_t smem_u32(const void* p) {
    uint32_t a;
    asm("{ .reg .u64 t; cvta.to.shared.u64 t, %1; cvt.u32.u64 %0, t; }" : "=r"(a) : "l"(p));
    return a;
}

// ---------------- init: zero scratch + build bf16 transposed W ----------------
__global__ void init_kernel(const float* __restrict__ gcn_w) {
    int idx = blockIdx.x * blockDim.x + threadIdx.x;
    int stride = gridDim.x * blockDim.x;
    for (int i = idx; i < N_NODES; i += stride) { g_deg_out[i] = 0; g_deg_in[i] = 0; }
    for (int i = idx; i < (NLAY + 1) * N_GRAPHS * D; i += stride) g_pooled[i] = 0.f;
    for (int i = idx; i < NLAY * D; i += stride) { g_bn_sum[i] = 0.f; g_bn_sq[i] = 0.f; }
    for (int i = idx; i < NLAY * D * D; i += stride) {
        int l = i / (D * D);
        int kn = i % (D * D);
        int k = kn / D, n = kn % D;
        size_t t = (size_t)l * D * D + (size_t)n * D + k;   // transposed: B[n][k] = W[k][n]
        g_Bh[t] = __float2bfloat16_rn(gcn_w[i]);
    }
}

// ---------------- degrees ----------------
__global__ void degree_kernel(const int* __restrict__ src, const int* __restrict__ dst) {
    int e = blockIdx.x * blockDim.x + threadIdx.x;
    if (e < N_EDGES) {
        atomicAdd(&g_deg_out[src[e]], 1);
        atomicAdd(&g_deg_in[dst[e]], 1);
    }
}

// ---------------- fused: norms + per-block partial sums of in-degree ----------------
__global__ void scan_partial_kernel() {
    __shared__ int sm[512];
    int t = threadIdx.x;
    int gi = blockIdx.x * 512 + t;
    int din = 0;
    if (gi < N_NODES) {
        int dout = g_deg_out[gi];
        din = g_deg_in[gi];
        g_norm_out[gi] = rsqrtf((float)max(dout, 1));
        g_norm_in[gi]  = rsqrtf((float)max(din, 1));
    }
    sm[t] = din;
    __syncthreads();
    for (int off = 256; off; off >>= 1) {
        if (t < off) sm[t] += sm[t + off];
        __syncthreads();
    }
    if (t == 0) g_partials[blockIdx.x] = sm[0];
}

__global__ void scan_offsets_kernel() {
    __shared__ int sa[256], sb[256];
    int t = threadIdx.x;
    int v = (t < SCAN_BLKS) ? g_partials[t] : 0;
    sa[t] = v;
    __syncthreads();
    int* in = sa; int* ot = sb;
    for (int off = 1; off < 256; off <<= 1) {
        ot[t] = in[t] + ((t >= off) ? in[t - off] : 0);
        __syncthreads();
        int* tmp = in; in = ot; ot = tmp;
    }
    if (t < SCAN_BLKS) g_partials[t] = in[t] - v;   // exclusive
}

__global__ void scan_write_kernel() {
    __shared__ int sa[512], sb[512];
    int t = threadIdx.x;
    int gi = blockIdx.x * 512 + t;
    int v = (gi < N_NODES) ? g_deg_in[gi] : 0;
    sa[t] = v;
    __syncthreads();
    int* in = sa; int* ot = sb;
    for (int off = 1; off < 512; off <<= 1) {
        ot[t] = in[t] + ((t >= off) ? in[t - off] : 0);
        __syncthreads();
        int* tmp = in; in = ot; ot = tmp;
    }
    int incl = in[t];
    int base = g_partials[blockIdx.x];
    if (gi < N_NODES) {
        int ex = base + incl - v;
        g_row_ptr[gi] = ex;
        g_cursor[gi]  = ex;
    }
    if (gi == N_NODES - 1) g_row_ptr[N_NODES] = base + incl;
}

__global__ void fill_kernel(const int* __restrict__ src, const int* __restrict__ dst) {
    int e = blockIdx.x * blockDim.x + threadIdx.x;
    if (e < N_EDGES) {
        int pos = atomicAdd(&g_cursor[dst[e]], 1);
        g_csr_src[pos] = src[e];
    }
}

// ---------------- SpMM + on-the-fly BN/ReLU + residual: warp per node ----------------
// layer 0: hin = feat RAW. layer l>0: apply h = relu(a*x+c) with coeffs of layer l-1.
// Inner loop: groups of 4 edges with a prefetched next group => up to 8 LDG.128 in flight.
// Also writes bf16 sidecar g_Abf (the GEMM's MMA operand) — free conversion here.
__global__ void spmm_kernel(int layer, const float* __restrict__ feat) {
    int gtid = blockIdx.x * blockDim.x + threadIdx.x;
    int w = gtid >> 5;
    int lane = gtid & 31;
    if (w >= N_NODES) return;
    const float* hin = (layer == 0) ? feat : ((layer & 1) ? g_A : g_H);
    float* outp = (layer & 1) ? g_H : g_A;
    const float4* h4 = (const float4*)hin;
    const bool dorelu = (layer > 0);

    float4 a4 = make_float4(1.f, 1.f, 1.f, 1.f);
    float4 c4 = make_float4(0.f, 0.f, 0.f, 0.f);
    if (dorelu) {
        a4 = ((const float4*)(g_bn_a + (size_t)(layer - 1) * D))[lane];
        c4 = ((const float4*)(g_bn_c + (size_t)(layer - 1) * D))[lane];
    }

    int start = g_row_ptr[w];
    int end   = g_row_ptr[w + 1];
    float4 acc = make_float4(0.f, 0.f, 0.f, 0.f);
    for (int base = start; base < end; base += 32) {
        int n = min(32, end - base);
        int s = 0; float ns = 0.f;
        if (lane < n) {
            s = g_csr_src[base + lane];
            ns = g_norm_out[s];
        }
        // prologue: prefetch group 0 (up to 4 edges)
        float4 xa[4]; float na[4];
        int cnt = n < 4 ? n : 4;
#pragma unroll
        for (int k = 0; k < 4; k++) if (k < cnt) {
            int sj = __shfl_sync(0xffffffffu, s, k);
            na[k] = __shfl_sync(0xffffffffu, ns, k);
            xa[k] = h4[(size_t)sj * 32 + lane];
        }
        for (int j = 0; j < n; j += 4) {
            // prefetch next group while current group's loads are in flight
            float4 xb[4]; float nb[4];
            int rem = n - j - 4;
            int cnt1 = rem < 4 ? rem : 4;          // may be <= 0
#pragma unroll
            for (int k = 0; k < 4; k++) if (k < cnt1) {
                int sj = __shfl_sync(0xffffffffu, s, j + 4 + k);
                nb[k] = __shfl_sync(0xffffffffu, ns, j + 4 + k);
                xb[k] = h4[(size_t)sj * 32 + lane];
            }
            int cc = n - j; if (cc > 4) cc = 4;
#pragma unroll
            for (int k = 0; k < 4; k++) if (k < cc) {
                float hx = fmaf(xa[k].x, a4.x, c4.x);
                float hy = fmaf(xa[k].y, a4.y, c4.y);
                float hz = fmaf(xa[k].z, a4.z, c4.z);
                float hw = fmaf(xa[k].w, a4.w, c4.w);
                if (dorelu) {
                    hx = fmaxf(hx, 0.f); hy = fmaxf(hy, 0.f);
                    hz = fmaxf(hz, 0.f); hw = fmaxf(hw, 0.f);
                }
                acc.x = fmaf(hx, na[k], acc.x);
                acc.y = fmaf(hy, na[k], acc.y);
                acc.z = fmaf(hz, na[k], acc.z);
                acc.w = fmaf(hw, na[k], acc.w);
            }
#pragma unroll
            for (int k = 0; k < 4; k++) { xa[k] = xb[k]; na[k] = nb[k]; }
        }
    }
    float c = 0.9f * g_norm_in[w];
    float4 xv = h4[(size_t)w * 32 + lane];
    float4 hv;
    hv.x = fmaf(xv.x, a4.x, c4.x);
    hv.y = fmaf(xv.y, a4.y, c4.y);
    hv.z = fmaf(xv.z, a4.z, c4.z);
    hv.w = fmaf(xv.w, a4.w, c4.w);
    if (dorelu) {
        hv.x = fmaxf(hv.x, 0.f); hv.y = fmaxf(hv.y, 0.f);
        hv.z = fmaxf(hv.z, 0.f); hv.w = fmaxf(hv.w, 0.f);
    }
    float4 r;
    r.x = c * acc.x + 0.1f * hv.x;
    r.y = c * acc.y + 0.1f * hv.y;
    r.z = c * acc.z + 0.1f * hv.z;
    r.w = c * acc.w + 0.1f * hv.w;
    ((float4*)outp)[(size_t)w * 32 + lane] = r;
    // bf16 sidecar for the GEMM MMA operand (same rn rounding as before)
    __nv_bfloat162 b01 = __float22bfloat162_rn(make_float2(r.x, r.y));
    __nv_bfloat162 b23 = __float22bfloat162_rn(make_float2(r.z, r.w));
    uint2 packed;
    packed.x = *(uint32_t*)&b01;
    packed.y = *(uint32_t*)&b23;
    ((uint2*)g_Abf)[(size_t)w * 32 + lane] = packed;
}

// ======== GEMM: buf = (1-beta)*buf + beta*(buf@W) + bias, single bf16 MMA, exact identity ========
// smem layout (bytes)
#define SM_AHI    0
#define SM_WHI    32768
#define SM_BIAS   65536
#define SM_COLSUM 66048
#define SM_COLSQ  66560
#define SM_TOTAL  67072

// swizzled offset inside a 128x128-bf16 tile: row-major 256B rows, 16B chunks XOR row&7
__device__ __forceinline__ uint32_t sw_off(int row, int chunk) {
    return (uint32_t)(row * 256 + ((chunk ^ (row & 7)) << 4));
}

__device__ __forceinline__ void ldsm_x4(uint32_t addr, uint32_t& r0, uint32_t& r1,
                                        uint32_t& r2, uint32_t& r3) {
    asm volatile("ldmatrix.sync.aligned.m8n8.x4.shared.b16 {%0,%1,%2,%3}, [%4];"
                 : "=r"(r0), "=r"(r1), "=r"(r2), "=r"(r3) : "r"(addr));
}

__device__ __forceinline__ void mma_bf16(float* d, uint32_t a0, uint32_t a1, uint32_t a2,
                                         uint32_t a3, uint32_t b0, uint32_t b1) {
    asm volatile(
        "mma.sync.aligned.m16n8k16.row.col.f32.bf16.bf16.f32 "
        "{%0,%1,%2,%3}, {%4,%5,%6,%7}, {%8,%9}, {%0,%1,%2,%3};"
        : "+f"(d[0]), "+f"(d[1]), "+f"(d[2]), "+f"(d[3])
        : "r"(a0), "r"(a1), "r"(a2), "r"(a3), "r"(b0), "r"(b1));
}

__global__ void __launch_bounds__(256, 2) mma_gemm_kernel(int layer, const float* __restrict__ gcn_b) {
    extern __shared__ char smem[];
    uint32_t sb = smem_u32(smem);
    int tid = threadIdx.x;
    int wid = tid >> 5, lane = tid & 31;
    int r0 = blockIdx.x * 128;
    float* buf = (layer & 1) ? g_H : g_A;
    const float BETA = (float)log1p(1.0 / (double)D);
    const float OMB  = 1.0f - BETA;

    // zero col accumulators + stage bias
    if (tid < 128) {
        ((float*)(smem + SM_COLSUM))[tid] = 0.f;
        ((float*)(smem + SM_COLSQ))[tid]  = 0.f;
        ((float*)(smem + SM_BIAS))[tid]   = gcn_b[layer * D + tid];
    }

    // ---- stage W ([n][k] bf16) + A tile (bf16 sidecar) into swizzled smem ----
    {
        const uint4* Bh = (const uint4*)(g_Bh + (size_t)layer * D * D);
        const uint4* Ab = (const uint4*)g_Abf;
#pragma unroll
        for (int i = 0; i < 8; i++) {
            int u = tid + i * 256;          // 2048 uint4 total
            int m = u >> 4;                 // row (16 uint4 per 256B row)
            int c = u & 15;
            uint32_t off = sw_off(m, c);
            *(uint4*)(smem + SM_WHI + off) = Bh[u];
            int row = r0 + m;
            uint4 av = make_uint4(0, 0, 0, 0);
            if (row < N_NODES) av = Ab[(size_t)row * 16 + c];
            *(uint4*)(smem + SM_AHI + off) = av;
        }
    }
    __syncthreads();

    // warp tile: rows m0..m0+32, cols n0..n0+64
    int m0 = (wid & 3) * 32;
    int n0 = (wid >> 2) * 64;

    float acc[2][8][4];
#pragma unroll
    for (int mt = 0; mt < 2; mt++)
#pragma unroll
        for (int nt = 0; nt < 8; nt++)
#pragma unroll
            for (int q = 0; q < 4; q++) acc[mt][nt][q] = 0.f;

    int lr = lane & 7;          // row within 8x8 matrix
    int lm = lane >> 3;         // which matrix (0..3)

#pragma unroll
    for (int kk = 0; kk < 8; kk++) {
        uint32_t ahi[2][4];
#pragma unroll
        for (int mt = 0; mt < 2; mt++) {
            int arow = m0 + mt * 16 + (lm & 1) * 8 + lr;
            int achk = kk * 2 + (lm >> 1);
            ldsm_x4(sb + SM_AHI + sw_off(arow, achk),
                    ahi[mt][0], ahi[mt][1], ahi[mt][2], ahi[mt][3]);
        }
        uint32_t bhi[8][2];
#pragma unroll
        for (int jp = 0; jp < 4; jp++) {
            int brow = n0 + jp * 16 + (lm >> 1) * 8 + lr;
            int bchk = kk * 2 + (lm & 1);
            ldsm_x4(sb + SM_WHI + sw_off(brow, bchk),
                    bhi[jp * 2][0], bhi[jp * 2][1], bhi[jp * 2 + 1][0], bhi[jp * 2 + 1][1]);
        }
#pragma unroll
        for (int mt = 0; mt < 2; mt++)
#pragma unroll
            for (int nt = 0; nt < 8; nt++)
                mma_bf16(acc[mt][nt], ahi[mt][0], ahi[mt][1], ahi[mt][2], ahi[mt][3],
                         bhi[nt][0], bhi[nt][1]);
    }

    // ---- epilogue: out = (1-b)*A(fp32, exact) + b*acc + bias; store; fused BN sums ----
    float* bias = (float*)(smem + SM_BIAS);
    float* colsum = (float*)(smem + SM_COLSUM);
    float* colsq  = (float*)(smem + SM_COLSQ);
    int rl = lane >> 2;                 // row-in-tile 0..7
    int cl = (lane & 3) * 2;            // col pair base (even)

#pragma unroll
    for (int nt = 0; nt < 8; nt++) {
        int col = n0 + nt * 8 + cl;
        float b0v = bias[col], b1v = bias[col + 1];
        float s0 = 0.f, s1 = 0.f, q0 = 0.f, q1 = 0.f;
#pragma unroll
        for (int mt = 0; mt < 2; mt++) {
            int rlo = r0 + m0 + mt * 16 + rl;
            int rhi = rlo + 8;
            if (rlo < N_NODES) {
                float2 ga = *(const float2*)&buf[(size_t)rlo * D + col];
                float c0 = fmaf(BETA, acc[mt][nt][0], fmaf(OMB, ga.x, b0v));
                float c1 = fmaf(BETA, acc[mt][nt][1], fmaf(OMB, ga.y, b1v));
                *(float2*)&buf[(size_t)rlo * D + col] = make_float2(c0, c1);
                s0 += c0; s1 += c1;
                q0 = fmaf(c0, c0, q0); q1 = fmaf(c1, c1, q1);
            }
            if (rhi < N_NODES) {
                float2 ga = *(const float2*)&buf[(size_t)rhi * D + col];
                float c2 = fmaf(BETA, acc[mt][nt][2], fmaf(OMB, ga.x, b0v));
                float c3 = fmaf(BETA, acc[mt][nt][3], fmaf(OMB, ga.y, b1v));
                *(float2*)&buf[(size_t)rhi * D + col] = make_float2(c2, c3);
                s0 += c2; s1 += c3;
                q0 = fmaf(c2, c2, q0); q1 = fmaf(c3, c3, q1);
            }
        }
#pragma unroll
        for (int s = 4; s < 32; s <<= 1) {
            s0 += __shfl_xor_sync(0xffffffffu, s0, s);
            s1 += __shfl_xor_sync(0xffffffffu, s1, s);
            q0 += __shfl_xor_sync(0xffffffffu, q0, s);
            q1 += __shfl_xor_sync(0xffffffffu, q1, s);
        }
        if (lane < 4) {
            atomicAdd(&colsum[col], s0);
            atomicAdd(&colsum[col + 1], s1);
            atomicAdd(&colsq[col], q0);
            atomicAdd(&colsq[col + 1], q1);
        }
    }
    __syncthreads();
    if (tid < 128) {
        atomicAdd(&g_bn_sum[layer * D + tid], colsum[tid]);
        atomicAdd(&g_bn_sq[layer * D + tid], colsq[tid]);
    }
}

// ---------------- pool (with inlined BN finalize): h_l = relu(bn_l(buf)) -> pooled[l+1] ----------------
__global__ void pool_kernel(int layer, const int* __restrict__ graph_id,
                            const float* __restrict__ bn_g, const float* __restrict__ bn_b) {
    int t = threadIdx.x;
    int v0 = blockIdx.x * 128;
    const float* buf = (layer & 1) ? g_H : g_A;

    // every block computes the BN coefficients (cheap, redundant, no extra launch)
    float inv_n = 1.0f / (float)N_NODES;
    float mu  = g_bn_sum[layer * D + t] * inv_n;
    float var = g_bn_sq[layer * D + t] * inv_n - mu * mu;
    float inv = rsqrtf(var + 1e-5f);
    float a = inv * bn_g[layer * D + t];
    float c = bn_b[layer * D + t] - mu * a;
    if (blockIdx.x == 0) {              // persist for next layer's spmm
        g_bn_a[layer * D + t] = a;
        g_bn_c[layer * D + t] = c;
    }

    float* pool = g_pooled + (size_t)(layer + 1) * N_GRAPHS * D;
    float acc = 0.f;
    int gprev = graph_id[v0];
    for (int r = 0; r < 128; r++) {
        int v = v0 + r;
        if (v >= N_NODES) break;
        int g = graph_id[v];
        if (g != gprev) {
            atomicAdd(&pool[(size_t)gprev * D + t], acc);
            acc = 0.f;
            gprev = g;
        }
        float x = buf[(size_t)v * D + t];
        acc += fmaxf(fmaf(x, a, c), 0.f);
    }
    atomicAdd(&pool[(size_t)gprev * D + t], acc);
}

__global__ void pool_feat_kernel(const float* __restrict__ feat,
                                 const int* __restrict__ graph_id) {
    int t = threadIdx.x;
    int v0 = blockIdx.x * 128;
    float acc = 0.f;
    int gprev = graph_id[v0];
    for (int r = 0; r < 128; r++) {
        int v = v0 + r;
        if (v >= N_NODES) break;
        int g = graph_id[v];
        if (g != gprev) {
            atomicAdd(&g_pooled[(size_t)gprev * D + t], acc);
            acc = 0.f;
            gprev = g;
        }
        acc += feat[(size_t)v * D + t];
    }
    atomicAdd(&g_pooled[(size_t)gprev * D + t], acc);
}

// ---------------- head: score, log_softmax, mean_pooled ----------------
__global__ void head_kernel(const float* __restrict__ lin_w,
                            const float* __restrict__ lin_b,
                            float* __restrict__ out) {
    int g = blockIdx.x;
    int t = threadIdx.x;
    int lane = t & 31;
    __shared__ float red[OUTC];
    if (t < OUTC) red[t] = 0.f;
    __syncthreads();

    float p[NLAY + 1];
#pragma unroll
    for (int i = 0; i < NLAY + 1; i++)
        p[i] = g_pooled[(size_t)i * N_GRAPHS * D + (size_t)g * D + t];

    out[N_GRAPHS * OUTC + (size_t)g * D + t] =
        0.2f * (p[1] + p[2] + p[3] + p[4] + p[5]);

    float part[OUTC];
#pragma unroll
    for (int o = 0; o < OUTC; o++) part[o] = 0.f;
#pragma unroll
    for (int i = 0; i < NLAY + 1; i++) {
        const float* lw = lin_w + (size_t)i * D * OUTC + (size_t)t * OUTC;
#pragma unroll
        for (int o = 0; o < OUTC; o++) part[o] = fmaf(p[i], lw[o], part[o]);
    }
#pragma unroll
    for (int o = 0; o < OUTC; o++) {
        float v = part[o];
        for (int off = 16; off; off >>= 1) v += __shfl_down_sync(0xffffffffu, v, off);
        if (lane == 0) atomicAdd(&red[o], v);
    }
    __syncthreads();
    if (t == 0) {
        float s[OUTC];
        float mx = -1e30f;
        for (int o = 0; o < OUTC; o++) {
            float b = 0.f;
            for (int i = 0; i < NLAY + 1; i++) b += lin_b[i * OUTC + o];
            s[o] = red[o] + b;
            mx = fmaxf(mx, s[o]);
        }
        float lse = 0.f;
        for (int o = 0; o < OUTC; o++) lse += expf(s[o] - mx);
        lse = logf(lse) + mx;
        for (int o = 0; o < OUTC; o++) out[(size_t)g * OUTC + o] = s[o] - lse;
    }
}

// ---------------- launch ----------------
extern "C" void kernel_launch(void* const* d_in, const int* in_sizes, int n_in,
                              void* d_out, int out_size) {
    const float* feat     = (const float*)d_in[0];
    const int*   src      = (const int*)d_in[1];
    const int*   dst      = (const int*)d_in[2];
    const int*   graph_id = (const int*)d_in[3];
    const float* gcn_w    = (const float*)d_in[4];
    const float* gcn_b    = (const float*)d_in[5];
    const float* bn_g     = (const float*)d_in[6];
    const float* bn_b     = (const float*)d_in[7];
    const float* lin_w    = (const float*)d_in[8];
    const float* lin_b    = (const float*)d_in[9];
    float* out = (float*)d_out;

    cudaFuncSetAttribute(mma_gemm_kernel, cudaFuncAttributeMaxDynamicSharedMemorySize, SM_TOTAL);

    init_kernel<<<512, 256>>>(gcn_w);
    degree_kernel<<<(N_EDGES + 255) / 256, 256>>>(src, dst);
    scan_partial_kernel<<<SCAN_BLKS, 512>>>();        // + norms
    scan_offsets_kernel<<<1, 256>>>();
    scan_write_kernel<<<SCAN_BLKS, 512>>>();
    fill_kernel<<<(N_EDGES + 255) / 256, 256>>>(src, dst);
    pool_feat_kernel<<<(N_NODES + 127) / 128, 128>>>(feat, graph_id);

    int spmm_blocks = (N_NODES * 32 + 255) / 256;
    int row_blocks  = (N_NODES + 127) / 128;
    for (int l = 0; l < NLAY; l++) {
        spmm_kernel<<<spmm_blocks, 256>>>(l, feat);
        mma_gemm_kernel<<<row_blocks, 256, SM_TOTAL>>>(l, gcn_b);
        pool_kernel<<<row_blocks, 128>>>(l, graph_id, bn_g, bn_b);
    }
    head_kernel<<<N_GRAPHS, 128>>>(lin_w, lin_b, out);
}

// round 13
// speedup vs baseline: 1.6137x; 1.6137x over previous
#include <cuda_runtime.h>
#include <cuda_bf16.h>
#include <math.h>
#include <stdint.h>

#define N_NODES 100000
#define N_EDGES 600000
#define D       128
#define OUTC    10
#define NLAY    5
#define N_GRAPHS 200
#define SCAN_BLKS 196   // ceil(100000/512)

// ---------------- device scratch (no allocations allowed) ----------------
// ping-pong activation buffers (pre-BN values)
__device__ __align__(128) float g_A[(size_t)N_NODES * D];
__device__ __align__(128) float g_H[(size_t)N_NODES * D];
__device__ __align__(128) __nv_bfloat16 g_Abf[(size_t)N_NODES * D];  // bf16 sidecar of GEMM input
__device__ int   g_deg_out[N_NODES];
__device__ int   g_deg_in[N_NODES];
__device__ float g_norm_out[N_NODES];
__device__ float g_norm_in[N_NODES];
__device__ int   g_row_ptr[N_NODES + 1];
__device__ int   g_cursor[N_NODES];
__device__ int   g_csr_src[N_EDGES];
__device__ int   g_partials[256];
__device__ __nv_bfloat16 g_Bh[NLAY * D * D];   // W transposed [l][n][k], bf16
__device__ float g_pooled[(NLAY + 1) * N_GRAPHS * D];
__device__ float g_bn_sum[NLAY * D];
__device__ float g_bn_sq[NLAY * D];
__device__ float g_bn_a[NLAY * D];
__device__ float g_bn_c[NLAY * D];

__device__ __forceinline__ uint32_t smem_u32(const void* p) {
    uint32_t a;
    asm("{ .reg .u64 t; cvta.to.shared.u64 t, %1; cvt.u32.u64 %0, t; }" : "=r"(a) : "l"(p));
    return a;
}

// ---------------- init: zero scratch + build bf16 transposed W ----------------
__global__ void init_kernel(const float* __restrict__ gcn_w) {
    int idx = blockIdx.x * blockDim.x + threadIdx.x;
    int stride = gridDim.x * blockDim.x;
    for (int i = idx; i < N_NODES; i += stride) { g_deg_out[i] = 0; g_deg_in[i] = 0; }
    for (int i = idx; i < (NLAY + 1) * N_GRAPHS * D; i += stride) g_pooled[i] = 0.f;
    for (int i = idx; i < NLAY * D; i += stride) { g_bn_sum[i] = 0.f; g_bn_sq[i] = 0.f; }
    for (int i = idx; i < NLAY * D * D; i += stride) {
        int l = i / (D * D);
        int kn = i % (D * D);
        int k = kn / D, n = kn % D;
        size_t t = (size_t)l * D * D + (size_t)n * D + k;   // transposed: B[n][k] = W[k][n]
        g_Bh[t] = __float2bfloat16_rn(gcn_w[i]);
    }
}

// ---------------- degrees ----------------
__global__ void degree_kernel(const int* __restrict__ src, const int* __restrict__ dst) {
    int e = blockIdx.x * blockDim.x + threadIdx.x;
    if (e < N_EDGES) {
        atomicAdd(&g_deg_out[src[e]], 1);
        atomicAdd(&g_deg_in[dst[e]], 1);
    }
}

// ---------------- fused: norms + per-block partial sums of in-degree ----------------
__global__ void scan_partial_kernel() {
    __shared__ int sm[512];
    int t = threadIdx.x;
    int gi = blockIdx.x * 512 + t;
    int din = 0;
    if (gi < N_NODES) {
        int dout = g_deg_out[gi];
        din = g_deg_in[gi];
        g_norm_out[gi] = rsqrtf((float)max(dout, 1));
        g_norm_in[gi]  = rsqrtf((float)max(din, 1));
    }
    sm[t] = din;
    __syncthreads();
    for (int off = 256; off; off >>= 1) {
        if (t < off) sm[t] += sm[t + off];
        __syncthreads();
    }
    if (t == 0) g_partials[blockIdx.x] = sm[0];
}

__global__ void scan_offsets_kernel() {
    __shared__ int sa[256], sb[256];
    int t = threadIdx.x;
    int v = (t < SCAN_BLKS) ? g_partials[t] : 0;
    sa[t] = v;
    __syncthreads();
    int* in = sa; int* ot = sb;
    for (int off = 1; off < 256; off <<= 1) {
        ot[t] = in[t] + ((t >= off) ? in[t - off] : 0);
        __syncthreads();
        int* tmp = in; in = ot; ot = tmp;
    }
    if (t < SCAN_BLKS) g_partials[t] = in[t] - v;   // exclusive
}

__global__ void scan_write_kernel() {
    __shared__ int sa[512], sb[512];
    int t = threadIdx.x;
    int gi = blockIdx.x * 512 + t;
    int v = (gi < N_NODES) ? g_deg_in[gi] : 0;
    sa[t] = v;
    __syncthreads();
    int* in = sa; int* ot = sb;
    for (int off = 1; off < 512; off <<= 1) {
        ot[t] = in[t] + ((t >= off) ? in[t - off] : 0);
        __syncthreads();
        int* tmp = in; in = ot; ot = tmp;
    }
    int incl = in[t];
    int base = g_partials[blockIdx.x];
    if (gi < N_NODES) {
        int ex = base + incl - v;
        g_row_ptr[gi] = ex;
        g_cursor[gi]  = ex;
    }
    if (gi == N_NODES - 1) g_row_ptr[N_NODES] = base + incl;
}

__global__ void fill_kernel(const int* __restrict__ src, const int* __restrict__ dst) {
    int e = blockIdx.x * blockDim.x + threadIdx.x;
    if (e < N_EDGES) {
        int pos = atomicAdd(&g_cursor[dst[e]], 1);
        g_csr_src[pos] = src[e];
    }
}

// ---------------- SpMM + on-the-fly BN/ReLU + residual: warp per node ----------------
// layer 0: hin = feat, used RAW (no BN, no ReLU).
// layer l>0: hin = prev pre-BN buffer; apply h = relu(a*x + c) with coeffs of layer l-1.
// Inner loop software-pipelined depth 1 (verified R11 structure).
// Epilogue also writes bf16 sidecar g_Abf = GEMM MMA operand (same rn rounding).
__global__ void spmm_kernel(int layer, const float* __restrict__ feat) {
    int gtid = blockIdx.x * blockDim.x + threadIdx.x;
    int w = gtid >> 5;
    int lane = gtid & 31;
    if (w >= N_NODES) return;
    const float* hin = (layer == 0) ? feat : ((layer & 1) ? g_A : g_H);
    float* outp = (layer & 1) ? g_H : g_A;
    const float4* h4 = (const float4*)hin;
    const bool dorelu = (layer > 0);

    float4 a4 = make_float4(1.f, 1.f, 1.f, 1.f);
    float4 c4 = make_float4(0.f, 0.f, 0.f, 0.f);
    if (dorelu) {
        a4 = ((const float4*)(g_bn_a + (size_t)(layer - 1) * D))[lane];
        c4 = ((const float4*)(g_bn_c + (size_t)(layer - 1) * D))[lane];
    }

    int start = g_row_ptr[w];
    int end   = g_row_ptr[w + 1];
    float4 acc = make_float4(0.f, 0.f, 0.f, 0.f);
    for (int base = start; base < end; base += 32) {
        int n = min(32, end - base);
        int s = 0; float ns = 0.f;
        if (lane < n) {
            s = g_csr_src[base + lane];
            ns = g_norm_out[s];
        }
        // pipeline prologue: load edge 0
        int   sj = __shfl_sync(0xffffffffu, s, 0);
        float nj = __shfl_sync(0xffffffffu, ns, 0);
        float4 x = h4[(size_t)sj * 32 + lane];
        for (int j = 0; j < n; j++) {
            float nj1 = 0.f;
            float4 x1 = make_float4(0.f, 0.f, 0.f, 0.f);
            if (j + 1 < n) {                       // prefetch edge j+1
                int sj1 = __shfl_sync(0xffffffffu, s, j + 1);
                nj1 = __shfl_sync(0xffffffffu, ns, j + 1);
                x1 = h4[(size_t)sj1 * 32 + lane];
            }
            float hx = fmaf(x.x, a4.x, c4.x);
            float hy = fmaf(x.y, a4.y, c4.y);
            float hz = fmaf(x.z, a4.z, c4.z);
            float hw = fmaf(x.w, a4.w, c4.w);
            if (dorelu) {
                hx = fmaxf(hx, 0.f); hy = fmaxf(hy, 0.f);
                hz = fmaxf(hz, 0.f); hw = fmaxf(hw, 0.f);
            }
            acc.x = fmaf(hx, nj, acc.x);
            acc.y = fmaf(hy, nj, acc.y);
            acc.z = fmaf(hz, nj, acc.z);
            acc.w = fmaf(hw, nj, acc.w);
            x = x1; nj = nj1;
        }
    }
    float c = 0.9f * g_norm_in[w];
    float4 xv = h4[(size_t)w * 32 + lane];
    float4 hv;
    hv.x = fmaf(xv.x, a4.x, c4.x);
    hv.y = fmaf(xv.y, a4.y, c4.y);
    hv.z = fmaf(xv.z, a4.z, c4.z);
    hv.w = fmaf(xv.w, a4.w, c4.w);
    if (dorelu) {
        hv.x = fmaxf(hv.x, 0.f); hv.y = fmaxf(hv.y, 0.f);
        hv.z = fmaxf(hv.z, 0.f); hv.w = fmaxf(hv.w, 0.f);
    }
    float4 r;
    r.x = c * acc.x + 0.1f * hv.x;
    r.y = c * acc.y + 0.1f * hv.y;
    r.z = c * acc.z + 0.1f * hv.z;
    r.w = c * acc.w + 0.1f * hv.w;
    ((float4*)outp)[(size_t)w * 32 + lane] = r;
    // bf16 sidecar for the GEMM MMA operand
    __nv_bfloat162 b01 = __float22bfloat162_rn(make_float2(r.x, r.y));
    __nv_bfloat162 b23 = __float22bfloat162_rn(make_float2(r.z, r.w));
    uint2 packed;
    packed.x = *(uint32_t*)&b01;
    packed.y = *(uint32_t*)&b23;
    ((uint2*)g_Abf)[(size_t)w * 32 + lane] = packed;
}

// ======== GEMM: buf = (1-beta)*buf + beta*(buf@W) + bias, single bf16 MMA, exact identity ========
// smem layout (bytes)
#define SM_AHI    0
#define SM_WHI    32768
#define SM_BIAS   65536
#define SM_COLSUM 66048
#define SM_COLSQ  66560
#define SM_TOTAL  67072

// swizzled offset inside a 128x128-bf16 tile: row-major 256B rows, 16B chunks XOR row&7
__device__ __forceinline__ uint32_t sw_off(int row, int chunk) {
    return (uint32_t)(row * 256 + ((chunk ^ (row & 7)) << 4));
}

__device__ __forceinline__ void ldsm_x4(uint32_t addr, uint32_t& r0, uint32_t& r1,
                                        uint32_t& r2, uint32_t& r3) {
    asm volatile("ldmatrix.sync.aligned.m8n8.x4.shared.b16 {%0,%1,%2,%3}, [%4];"
                 : "=r"(r0), "=r"(r1), "=r"(r2), "=r"(r3) : "r"(addr));
}

__device__ __forceinline__ void mma_bf16(float* d, uint32_t a0, uint32_t a1, uint32_t a2,
                                         uint32_t a3, uint32_t b0, uint32_t b1) {
    asm volatile(
        "mma.sync.aligned.m16n8k16.row.col.f32.bf16.bf16.f32 "
        "{%0,%1,%2,%3}, {%4,%5,%6,%7}, {%8,%9}, {%0,%1,%2,%3};"
        : "+f"(d[0]), "+f"(d[1]), "+f"(d[2]), "+f"(d[3])
        : "r"(a0), "r"(a1), "r"(a2), "r"(a3), "r"(b0), "r"(b1));
}

__global__ void __launch_bounds__(256, 2) mma_gemm_kernel(int layer, const float* __restrict__ gcn_b) {
    extern __shared__ char smem[];
    uint32_t sb = smem_u32(smem);
    int tid = threadIdx.x;
    int wid = tid >> 5, lane = tid & 31;
    int r0 = blockIdx.x * 128;
    float* buf = (layer & 1) ? g_H : g_A;
    const float BETA = (float)log1p(1.0 / (double)D);
    const float OMB  = 1.0f - BETA;

    // zero col accumulators + stage bias
    if (tid < 128) {
        ((float*)(smem + SM_COLSUM))[tid] = 0.f;
        ((float*)(smem + SM_COLSQ))[tid]  = 0.f;
        ((float*)(smem + SM_BIAS))[tid]   = gcn_b[layer * D + tid];
    }

    // ---- stage W ([n][k] bf16) + A tile (bf16 sidecar, no conversion) into swizzled smem ----
    {
        const uint4* Bh = (const uint4*)(g_Bh + (size_t)layer * D * D);
        const uint4* Ab = (const uint4*)g_Abf;
#pragma unroll
        for (int i = 0; i < 8; i++) {
            int u = tid + i * 256;          // 2048 uint4 total
            int m = u >> 4;                 // row (16 uint4 per 256B row)
            int c = u & 15;
            uint32_t off = sw_off(m, c);
            *(uint4*)(smem + SM_WHI + off) = Bh[u];
            int row = r0 + m;
            uint4 av = make_uint4(0, 0, 0, 0);
            if (row < N_NODES) av = Ab[(size_t)row * 16 + c];
            *(uint4*)(smem + SM_AHI + off) = av;
        }
    }
    __syncthreads();

    // warp tile: rows m0..m0+32, cols n0..n0+64
    int m0 = (wid & 3) * 32;
    int n0 = (wid >> 2) * 64;

    float acc[2][8][4];
#pragma unroll
    for (int mt = 0; mt < 2; mt++)
#pragma unroll
        for (int nt = 0; nt < 8; nt++)
#pragma unroll
            for (int q = 0; q < 4; q++) acc[mt][nt][q] = 0.f;

    int lr = lane & 7;          // row within 8x8 matrix
    int lm = lane >> 3;         // which matrix (0..3)

#pragma unroll
    for (int kk = 0; kk < 8; kk++) {
        uint32_t ahi[2][4];
#pragma unroll
        for (int mt = 0; mt < 2; mt++) {
            int arow = m0 + mt * 16 + (lm & 1) * 8 + lr;
            int achk = kk * 2 + (lm >> 1);
            ldsm_x4(sb + SM_AHI + sw_off(arow, achk),
                    ahi[mt][0], ahi[mt][1], ahi[mt][2], ahi[mt][3]);
        }
        uint32_t bhi[8][2];
#pragma unroll
        for (int jp = 0; jp < 4; jp++) {
            int brow = n0 + jp * 16 + (lm >> 1) * 8 + lr;
            int bchk = kk * 2 + (lm & 1);
            ldsm_x4(sb + SM_WHI + sw_off(brow, bchk),
                    bhi[jp * 2][0], bhi[jp * 2][1], bhi[jp * 2 + 1][0], bhi[jp * 2 + 1][1]);
        }
#pragma unroll
        for (int mt = 0; mt < 2; mt++)
#pragma unroll
            for (int nt = 0; nt < 8; nt++)
                mma_bf16(acc[mt][nt], ahi[mt][0], ahi[mt][1], ahi[mt][2], ahi[mt][3],
                         bhi[nt][0], bhi[nt][1]);
    }

    // ---- epilogue: out = (1-b)*A(fp32, exact) + b*acc + bias; store; fused BN sums ----
    float* bias = (float*)(smem + SM_BIAS);
    float* colsum = (float*)(smem + SM_COLSUM);
    float* colsq  = (float*)(smem + SM_COLSQ);
    int rl = lane >> 2;                 // row-in-tile 0..7
    int cl = (lane & 3) * 2;            // col pair base (even)

#pragma unroll
    for (int nt = 0; nt < 8; nt++) {
        int col = n0 + nt * 8 + cl;
        float b0v = bias[col], b1v = bias[col + 1];
        float s0 = 0.f, s1 = 0.f, q0 = 0.f, q1 = 0.f;
#pragma unroll
        for (int mt = 0; mt < 2; mt++) {
            int rlo = r0 + m0 + mt * 16 + rl;
            int rhi = rlo + 8;
            if (rlo < N_NODES) {
                float2 ga = *(const float2*)&buf[(size_t)rlo * D + col];
                float c0 = fmaf(BETA, acc[mt][nt][0], fmaf(OMB, ga.x, b0v));
                float c1 = fmaf(BETA, acc[mt][nt][1], fmaf(OMB, ga.y, b1v));
                *(float2*)&buf[(size_t)rlo * D + col] = make_float2(c0, c1);
                s0 += c0; s1 += c1;
                q0 = fmaf(c0, c0, q0); q1 = fmaf(c1, c1, q1);
            }
            if (rhi < N_NODES) {
                float2 ga = *(const float2*)&buf[(size_t)rhi * D + col];
                float c2 = fmaf(BETA, acc[mt][nt][2], fmaf(OMB, ga.x, b0v));
                float c3 = fmaf(BETA, acc[mt][nt][3], fmaf(OMB, ga.y, b1v));
                *(float2*)&buf[(size_t)rhi * D + col] = make_float2(c2, c3);
                s0 += c2; s1 += c3;
                q0 = fmaf(c2, c2, q0); q1 = fmaf(c3, c3, q1);
            }
        }
#pragma unroll
        for (int s = 4; s < 32; s <<= 1) {
            s0 += __shfl_xor_sync(0xffffffffu, s0, s);
            s1 += __shfl_xor_sync(0xffffffffu, s1, s);
            q0 += __shfl_xor_sync(0xffffffffu, q0, s);
            q1 += __shfl_xor_sync(0xffffffffu, q1, s);
        }
        if (lane < 4) {
            atomicAdd(&colsum[col], s0);
            atomicAdd(&colsum[col + 1], s1);
            atomicAdd(&colsq[col], q0);
            atomicAdd(&colsq[col + 1], q1);
        }
    }
    __syncthreads();
    if (tid < 128) {
        atomicAdd(&g_bn_sum[layer * D + tid], colsum[tid]);
        atomicAdd(&g_bn_sq[layer * D + tid], colsq[tid]);
    }
}

// ---------------- pool (with inlined BN finalize): h_l = relu(bn_l(buf)) -> pooled[l+1] ----------------
__global__ void pool_kernel(int layer, const int* __restrict__ graph_id,
                            const float* __restrict__ bn_g, const float* __restrict__ bn_b) {
    int t = threadIdx.x;
    int v0 = blockIdx.x * 128;
    const float* buf = (layer & 1) ? g_H : g_A;

    // every block computes the BN coefficients (cheap, redundant, no extra launch)
    float inv_n = 1.0f / (float)N_NODES;
    float mu  = g_bn_sum[layer * D + t] * inv_n;
    float var = g_bn_sq[layer * D + t] * inv_n - mu * mu;
    float inv = rsqrtf(var + 1e-5f);
    float a = inv * bn_g[layer * D + t];
    float c = bn_b[layer * D + t] - mu * a;
    if (blockIdx.x == 0) {              // persist for next layer's spmm
        g_bn_a[layer * D + t] = a;
        g_bn_c[layer * D + t] = c;
    }

    float* pool = g_pooled + (size_t)(layer + 1) * N_GRAPHS * D;
    float acc = 0.f;
    int gprev = graph_id[v0];
    for (int r = 0; r < 128; r++) {
        int v = v0 + r;
        if (v >= N_NODES) break;
        int g = graph_id[v];
        if (g != gprev) {
            atomicAdd(&pool[(size_t)gprev * D + t], acc);
            acc = 0.f;
            gprev = g;
        }
        float x = buf[(size_t)v * D + t];
        acc += fmaxf(fmaf(x, a, c), 0.f);
    }
    atomicAdd(&pool[(size_t)gprev * D + t], acc);
}

__global__ void pool_feat_kernel(const float* __restrict__ feat,
                                 const int* __restrict__ graph_id) {
    int t = threadIdx.x;
    int v0 = blockIdx.x * 128;
    float acc = 0.f;
    int gprev = graph_id[v0];
    for (int r = 0; r < 128; r++) {
        int v = v0 + r;
        if (v >= N_NODES) break;
        int g = graph_id[v];
        if (g != gprev) {
            atomicAdd(&g_pooled[(size_t)gprev * D + t], acc);
            acc = 0.f;
            gprev = g;
        }
        acc += feat[(size_t)v * D + t];
    }
    atomicAdd(&g_pooled[(size_t)gprev * D + t], acc);
}

// ---------------- head: score, log_softmax, mean_pooled ----------------
__global__ void head_kernel(const float* __restrict__ lin_w,
                            const float* __restrict__ lin_b,
                            float* __restrict__ out) {
    int g = blockIdx.x;
    int t = threadIdx.x;
    int lane = t & 31;
    __shared__ float red[OUTC];
    if (t < OUTC) red[t] = 0.f;
    __syncthreads();

    float p[NLAY + 1];
#pragma unroll
    for (int i = 0; i < NLAY + 1; i++)
        p[i] = g_pooled[(size_t)i * N_GRAPHS * D + (size_t)g * D + t];

    out[N_GRAPHS * OUTC + (size_t)g * D + t] =
        0.2f * (p[1] + p[2] + p[3] + p[4] + p[5]);

    float part[OUTC];
#pragma unroll
    for (int o = 0; o < OUTC; o++) part[o] = 0.f;
#pragma unroll
    for (int i = 0; i < NLAY + 1; i++) {
        const float* lw = lin_w + (size_t)i * D * OUTC + (size_t)t * OUTC;
#pragma unroll
        for (int o = 0; o < OUTC; o++) part[o] = fmaf(p[i], lw[o], part[o]);
    }
#pragma unroll
    for (int o = 0; o < OUTC; o++) {
        float v = part[o];
        for (int off = 16; off; off >>= 1) v += __shfl_down_sync(0xffffffffu, v, off);
        if (lane == 0) atomicAdd(&red[o], v);
    }
    __syncthreads();
    if (t == 0) {
        float s[OUTC];
        float mx = -1e30f;
        for (int o = 0; o < OUTC; o++) {
            float b = 0.f;
            for (int i = 0; i < NLAY + 1; i++) b += lin_b[i * OUTC + o];
            s[o] = red[o] + b;
            mx = fmaxf(mx, s[o]);
        }
        float lse = 0.f;
        for (int o = 0; o < OUTC; o++) lse += expf(s[o] - mx);
        lse = logf(lse) + mx;
        for (int o = 0; o < OUTC; o++) out[(size_t)g * OUTC + o] = s[o] - lse;
    }
}

// ---------------- launch ----------------
extern "C" void kernel_launch(void* const* d_in, const int* in_sizes, int n_in,
                              void* d_out, int out_size) {
    const float* feat     = (const float*)d_in[0];
    const int*   src      = (const int*)d_in[1];
    const int*   dst      = (const int*)d_in[2];
    const int*   graph_id = (const int*)d_in[3];
    const float* gcn_w    = (const float*)d_in[4];
    const float* gcn_b    = (const float*)d_in[5];
    const float* bn_g     = (const float*)d_in[6];
    const float* bn_b     = (const float*)d_in[7];
    const float* lin_w    = (const float*)d_in[8];
    const float* lin_b    = (const float*)d_in[9];
    float* out = (float*)d_out;

    cudaFuncSetAttribute(mma_gemm_kernel, cudaFuncAttributeMaxDynamicSharedMemorySize, SM_TOTAL);

    init_kernel<<<512, 256>>>(gcn_w);
    degree_kernel<<<(N_EDGES + 255) / 256, 256>>>(src, dst);
    scan_partial_kernel<<<SCAN_BLKS, 512>>>();        // + norms
    scan_offsets_kernel<<<1, 256>>>();
    scan_write_kernel<<<SCAN_BLKS, 512>>>();
    fill_kernel<<<(N_EDGES + 255) / 256, 256>>>(src, dst);
    pool_feat_kernel<<<(N_NODES + 127) / 128, 128>>>(feat, graph_id);

    int spmm_blocks = (N_NODES * 32 + 255) / 256;
    int row_blocks  = (N_NODES + 127) / 128;
    for (int l = 0; l < NLAY; l++) {
        spmm_kernel<<<spmm_blocks, 256>>>(l, feat);
        mma_gemm_kernel<<<row_blocks, 256, SM_TOTAL>>>(l, gcn_b);
        pool_kernel<<<row_blocks, 128>>>(l, graph_id, bn_g, bn_b);
    }
    head_kernel<<<N_GRAPHS, 128>>>(lin_w, lin_b, out);
}

// round 14
// speedup vs baseline: 1.6606x; 1.0291x over previous
#include <cuda_runtime.h>
#include <cuda_bf16.h>
#include <math.h>
#include <stdint.h>

#define N_NODES 100000
#define N_EDGES 600000
#define D       128
#define OUTC    10
#define NLAY    5
#define N_GRAPHS 200
#define SCAN_BLKS 196   // ceil(100000/512)

// ---------------- device scratch (no allocations allowed) ----------------
// ping-pong activation buffers (pre-BN values)
__device__ __align__(128) float g_A[(size_t)N_NODES * D];
__device__ __align__(128) float g_H[(size_t)N_NODES * D];
__device__ int   g_deg_out[N_NODES];
__device__ int   g_deg_in[N_NODES];
__device__ float g_norm_out[N_NODES];
__device__ float g_norm_in[N_NODES];
__device__ int   g_row_ptr[N_NODES + 1];
__device__ int   g_cursor[N_NODES];
__device__ int   g_csr_src[N_EDGES];
__device__ int   g_partials[256];
__device__ __nv_bfloat16 g_Bh[NLAY * D * D];   // W transposed [l][n][k], bf16
__device__ float g_pooled[(NLAY + 1) * N_GRAPHS * D];
__device__ float g_bn_sum[NLAY * D];
__device__ float g_bn_sq[NLAY * D];
__device__ float g_bn_a[NLAY * D];
__device__ float g_bn_c[NLAY * D];

__device__ __forceinline__ uint32_t smem_u32(const void* p) {
    uint32_t a;
    asm("{ .reg .u64 t; cvta.to.shared.u64 t, %1; cvt.u32.u64 %0, t; }" : "=r"(a) : "l"(p));
    return a;
}

// ---------------- init: zero scratch + build bf16 transposed W ----------------
__global__ void init_kernel(const float* __restrict__ gcn_w) {
    int idx = blockIdx.x * blockDim.x + threadIdx.x;
    int stride = gridDim.x * blockDim.x;
    for (int i = idx; i < N_NODES; i += stride) { g_deg_out[i] = 0; g_deg_in[i] = 0; }
    for (int i = idx; i < (NLAY + 1) * N_GRAPHS * D; i += stride) g_pooled[i] = 0.f;
    for (int i = idx; i < NLAY * D; i += stride) { g_bn_sum[i] = 0.f; g_bn_sq[i] = 0.f; }
    for (int i = idx; i < NLAY * D * D; i += stride) {
        int l = i / (D * D);
        int kn = i % (D * D);
        int k = kn / D, n = kn % D;
        size_t t = (size_t)l * D * D + (size_t)n * D + k;   // transposed: B[n][k] = W[k][n]
        g_Bh[t] = __float2bfloat16_rn(gcn_w[i]);
    }
}

// ---------------- degrees ----------------
__global__ void degree_kernel(const int* __restrict__ src, const int* __restrict__ dst) {
    int e = blockIdx.x * blockDim.x + threadIdx.x;
    if (e < N_EDGES) {
        atomicAdd(&g_deg_out[src[e]], 1);
        atomicAdd(&g_deg_in[dst[e]], 1);
    }
}

// ---------------- fused: norms + per-block partial sums of in-degree ----------------
__global__ void scan_partial_kernel() {
    __shared__ int sm[512];
    int t = threadIdx.x;
    int gi = blockIdx.x * 512 + t;
    int din = 0;
    if (gi < N_NODES) {
        int dout = g_deg_out[gi];
        din = g_deg_in[gi];
        g_norm_out[gi] = rsqrtf((float)max(dout, 1));
        g_norm_in[gi]  = rsqrtf((float)max(din, 1));
    }
    sm[t] = din;
    __syncthreads();
    for (int off = 256; off; off >>= 1) {
        if (t < off) sm[t] += sm[t + off];
        __syncthreads();
    }
    if (t == 0) g_partials[blockIdx.x] = sm[0];
}

// ---------------- scan_write with inlined cross-block offsets ----------------
// Each block redundantly reduces the partials with index < blockIdx.x (196 ints, cheap).
__global__ void scan_write_kernel() {
    __shared__ int sa[512], sb[512];
    __shared__ int s_base;
    int t = threadIdx.x;
    int bid = blockIdx.x;
    int gi = bid * 512 + t;

    // block-local exclusive base = sum of partials[b] for b < bid
    {
        int v = (t < SCAN_BLKS && t < bid) ? g_partials[t] : 0;
        sa[t] = v;
        __syncthreads();
        for (int off = 256; off; off >>= 1) {
            if (t < off) sa[t] += sa[t + off];
            __syncthreads();
        }
        if (t == 0) s_base = sa[0];
        __syncthreads();
    }

    int v = (gi < N_NODES) ? g_deg_in[gi] : 0;
    sa[t] = v;
    __syncthreads();
    int* in = sa; int* ot = sb;
    for (int off = 1; off < 512; off <<= 1) {
        ot[t] = in[t] + ((t >= off) ? in[t - off] : 0);
        __syncthreads();
        int* tmp = in; in = ot; ot = tmp;
    }
    int incl = in[t];
    int base = s_base;
    if (gi < N_NODES) {
        int ex = base + incl - v;
        g_row_ptr[gi] = ex;
        g_cursor[gi]  = ex;
    }
    if (gi == N_NODES - 1) g_row_ptr[N_NODES] = base + incl;
}

__global__ void fill_kernel(const int* __restrict__ src, const int* __restrict__ dst) {
    int e = blockIdx.x * blockDim.x + threadIdx.x;
    if (e < N_EDGES) {
        int pos = atomicAdd(&g_cursor[dst[e]], 1);
        g_csr_src[pos] = src[e];
    }
}

// ---------------- SpMM + on-the-fly BN/ReLU + residual: warp per node ----------------
// layer 0: hin = feat, used RAW (no BN, no ReLU).
// layer l>0: hin = prev pre-BN buffer; apply h = relu(a*x + c) with coeffs of layer l-1.
// Inner loop software-pipelined depth 1 (verified R11 structure).
__global__ void spmm_kernel(int layer, const float* __restrict__ feat) {
    int gtid = blockIdx.x * blockDim.x + threadIdx.x;
    int w = gtid >> 5;
    int lane = gtid & 31;
    if (w >= N_NODES) return;
    const float* hin = (layer == 0) ? feat : ((layer & 1) ? g_A : g_H);
    float* outp = (layer & 1) ? g_H : g_A;
    const float4* h4 = (const float4*)hin;
    const bool dorelu = (layer > 0);

    float4 a4 = make_float4(1.f, 1.f, 1.f, 1.f);
    float4 c4 = make_float4(0.f, 0.f, 0.f, 0.f);
    if (dorelu) {
        a4 = ((const float4*)(g_bn_a + (size_t)(layer - 1) * D))[lane];
        c4 = ((const float4*)(g_bn_c + (size_t)(layer - 1) * D))[lane];
    }

    int start = g_row_ptr[w];
    int end   = g_row_ptr[w + 1];
    float4 acc = make_float4(0.f, 0.f, 0.f, 0.f);
    for (int base = start; base < end; base += 32) {
        int n = min(32, end - base);
        int s = 0; float ns = 0.f;
        if (lane < n) {
            s = g_csr_src[base + lane];
            ns = g_norm_out[s];
        }
        // pipeline prologue: load edge 0
        int   sj = __shfl_sync(0xffffffffu, s, 0);
        float nj = __shfl_sync(0xffffffffu, ns, 0);
        float4 x = h4[(size_t)sj * 32 + lane];
        for (int j = 0; j < n; j++) {
            float nj1 = 0.f;
            float4 x1 = make_float4(0.f, 0.f, 0.f, 0.f);
            if (j + 1 < n) {                       // prefetch edge j+1
                int sj1 = __shfl_sync(0xffffffffu, s, j + 1);
                nj1 = __shfl_sync(0xffffffffu, ns, j + 1);
                x1 = h4[(size_t)sj1 * 32 + lane];
            }
            float hx = fmaf(x.x, a4.x, c4.x);
            float hy = fmaf(x.y, a4.y, c4.y);
            float hz = fmaf(x.z, a4.z, c4.z);
            float hw = fmaf(x.w, a4.w, c4.w);
            if (dorelu) {
                hx = fmaxf(hx, 0.f); hy = fmaxf(hy, 0.f);
                hz = fmaxf(hz, 0.f); hw = fmaxf(hw, 0.f);
            }
            acc.x = fmaf(hx, nj, acc.x);
            acc.y = fmaf(hy, nj, acc.y);
            acc.z = fmaf(hz, nj, acc.z);
            acc.w = fmaf(hw, nj, acc.w);
            x = x1; nj = nj1;
        }
    }
    float c = 0.9f * g_norm_in[w];
    float4 xv = h4[(size_t)w * 32 + lane];
    float4 hv;
    hv.x = fmaf(xv.x, a4.x, c4.x);
    hv.y = fmaf(xv.y, a4.y, c4.y);
    hv.z = fmaf(xv.z, a4.z, c4.z);
    hv.w = fmaf(xv.w, a4.w, c4.w);
    if (dorelu) {
        hv.x = fmaxf(hv.x, 0.f); hv.y = fmaxf(hv.y, 0.f);
        hv.z = fmaxf(hv.z, 0.f); hv.w = fmaxf(hv.w, 0.f);
    }
    float4 r;
    r.x = c * acc.x + 0.1f * hv.x;
    r.y = c * acc.y + 0.1f * hv.y;
    r.z = c * acc.z + 0.1f * hv.z;
    r.w = c * acc.w + 0.1f * hv.w;
    ((float4*)outp)[(size_t)w * 32 + lane] = r;
}

// ======== GEMM: buf = (1-beta)*buf + beta*(buf@W) + bias, single bf16 MMA, exact identity ========
// smem layout (bytes)
#define SM_AHI    0
#define SM_WHI    32768
#define SM_BIAS   65536
#define SM_COLSUM 66048
#define SM_COLSQ  66560
#define SM_TOTAL  67072

// swizzled offset inside a 128x128-bf16 tile: row-major 256B rows, 16B chunks XOR row&7
__device__ __forceinline__ uint32_t sw_off(int row, int chunk) {
    return (uint32_t)(row * 256 + ((chunk ^ (row & 7)) << 4));
}

__device__ __forceinline__ void ldsm_x4(uint32_t addr, uint32_t& r0, uint32_t& r1,
                                        uint32_t& r2, uint32_t& r3) {
    asm volatile("ldmatrix.sync.aligned.m8n8.x4.shared.b16 {%0,%1,%2,%3}, [%4];"
                 : "=r"(r0), "=r"(r1), "=r"(r2), "=r"(r3) : "r"(addr));
}

__device__ __forceinline__ void mma_bf16(float* d, uint32_t a0, uint32_t a1, uint32_t a2,
                                         uint32_t a3, uint32_t b0, uint32_t b1) {
    asm volatile(
        "mma.sync.aligned.m16n8k16.row.col.f32.bf16.bf16.f32 "
        "{%0,%1,%2,%3}, {%4,%5,%6,%7}, {%8,%9}, {%0,%1,%2,%3};"
        : "+f"(d[0]), "+f"(d[1]), "+f"(d[2]), "+f"(d[3])
        : "r"(a0), "r"(a1), "r"(a2), "r"(a3), "r"(b0), "r"(b1));
}

__global__ void __launch_bounds__(256, 2) mma_gemm_kernel(int layer, const float* __restrict__ gcn_b) {
    extern __shared__ char smem[];
    uint32_t sb = smem_u32(smem);
    int tid = threadIdx.x;
    int wid = tid >> 5, lane = tid & 31;
    int r0 = blockIdx.x * 128;
    float* buf = (layer & 1) ? g_H : g_A;
    const float BETA = (float)log1p(1.0 / (double)D);
    const float OMB  = 1.0f - BETA;

    // zero col accumulators + stage bias
    if (tid < 128) {
        ((float*)(smem + SM_COLSUM))[tid] = 0.f;
        ((float*)(smem + SM_COLSQ))[tid]  = 0.f;
        ((float*)(smem + SM_BIAS))[tid]   = gcn_b[layer * D + tid];
    }

    // ---- stage W ([n][k] bf16) into swizzled smem ----
    {
        const uint4* Bh = (const uint4*)(g_Bh + (size_t)layer * D * D);
#pragma unroll
        for (int i = 0; i < 8; i++) {
            int u = tid + i * 256;          // 2048 uint4 total
            int n = u >> 4;                 // 16 chunks per row
            int c = u & 15;
            *(uint4*)(smem + SM_WHI + sw_off(n, c)) = Bh[u];
        }
    }
    // ---- stage A tile (fp32 -> bf16, packed cvt) into swizzled smem ----
    {
        const float4* A4 = (const float4*)buf;
#pragma unroll
        for (int i = 0; i < 16; i++) {
            int j = tid + i * 256;          // 4096 float4 total
            int m = j >> 5;                 // 32 float4 per row
            int k4 = j & 31;
            int row = r0 + m;
            float4 x = (row < N_NODES) ? A4[(size_t)row * 32 + k4]
                                       : make_float4(0.f, 0.f, 0.f, 0.f);
            __nv_bfloat162 h01 = __float22bfloat162_rn(make_float2(x.x, x.y));
            __nv_bfloat162 h23 = __float22bfloat162_rn(make_float2(x.z, x.w));
            uint32_t off = sw_off(m, k4 >> 1) + (uint32_t)((k4 & 1) << 3);
            __nv_bfloat162* ph = (__nv_bfloat162*)(smem + SM_AHI + off);
            ph[0] = h01;
            ph[1] = h23;
        }
    }
    __syncthreads();

    // warp tile: rows m0..m0+32, cols n0..n0+64
    int m0 = (wid & 3) * 32;
    int n0 = (wid >> 2) * 64;

    float acc[2][8][4];
#pragma unroll
    for (int mt = 0; mt < 2; mt++)
#pragma unroll
        for (int nt = 0; nt < 8; nt++)
#pragma unroll
            for (int q = 0; q < 4; q++) acc[mt][nt][q] = 0.f;

    int lr = lane & 7;          // row within 8x8 matrix
    int lm = lane >> 3;         // which matrix (0..3)

#pragma unroll
    for (int kk = 0; kk < 8; kk++) {
        uint32_t ahi[2][4];
#pragma unroll
        for (int mt = 0; mt < 2; mt++) {
            int arow = m0 + mt * 16 + (lm & 1) * 8 + lr;
            int achk = kk * 2 + (lm >> 1);
            ldsm_x4(sb + SM_AHI + sw_off(arow, achk),
                    ahi[mt][0], ahi[mt][1], ahi[mt][2], ahi[mt][3]);
        }
        uint32_t bhi[8][2];
#pragma unroll
        for (int jp = 0; jp < 4; jp++) {
            int brow = n0 + jp * 16 + (lm >> 1) * 8 + lr;
            int bchk = kk * 2 + (lm & 1);
            ldsm_x4(sb + SM_WHI + sw_off(brow, bchk),
                    bhi[jp * 2][0], bhi[jp * 2][1], bhi[jp * 2 + 1][0], bhi[jp * 2 + 1][1]);
        }
#pragma unroll
        for (int mt = 0; mt < 2; mt++)
#pragma unroll
            for (int nt = 0; nt < 8; nt++)
                mma_bf16(acc[mt][nt], ahi[mt][0], ahi[mt][1], ahi[mt][2], ahi[mt][3],
                         bhi[nt][0], bhi[nt][1]);
    }

    // ---- epilogue: out = (1-b)*A(fp32, exact) + b*acc + bias; store; fused BN sums ----
    float* bias = (float*)(smem + SM_BIAS);
    float* colsum = (float*)(smem + SM_COLSUM);
    float* colsq  = (float*)(smem + SM_COLSQ);
    int rl = lane >> 2;                 // row-in-tile 0..7
    int cl = (lane & 3) * 2;            // col pair base (even)

#pragma unroll
    for (int nt = 0; nt < 8; nt++) {
        int col = n0 + nt * 8 + cl;
        float b0v = bias[col], b1v = bias[col + 1];
        float s0 = 0.f, s1 = 0.f, q0 = 0.f, q1 = 0.f;
#pragma unroll
        for (int mt = 0; mt < 2; mt++) {
            int rlo = r0 + m0 + mt * 16 + rl;
            int rhi = rlo + 8;
            if (rlo < N_NODES) {
                float2 ga = *(const float2*)&buf[(size_t)rlo * D + col];
                float c0 = fmaf(BETA, acc[mt][nt][0], fmaf(OMB, ga.x, b0v));
                float c1 = fmaf(BETA, acc[mt][nt][1], fmaf(OMB, ga.y, b1v));
                *(float2*)&buf[(size_t)rlo * D + col] = make_float2(c0, c1);
                s0 += c0; s1 += c1;
                q0 = fmaf(c0, c0, q0); q1 = fmaf(c1, c1, q1);
            }
            if (rhi < N_NODES) {
                float2 ga = *(const float2*)&buf[(size_t)rhi * D + col];
                float c2 = fmaf(BETA, acc[mt][nt][2], fmaf(OMB, ga.x, b0v));
                float c3 = fmaf(BETA, acc[mt][nt][3], fmaf(OMB, ga.y, b1v));
                *(float2*)&buf[(size_t)rhi * D + col] = make_float2(c2, c3);
                s0 += c2; s1 += c3;
                q0 = fmaf(c2, c2, q0); q1 = fmaf(c3, c3, q1);
            }
        }
#pragma unroll
        for (int s = 4; s < 32; s <<= 1) {
            s0 += __shfl_xor_sync(0xffffffffu, s0, s);
            s1 += __shfl_xor_sync(0xffffffffu, s1, s);
            q0 += __shfl_xor_sync(0xffffffffu, q0, s);
            q1 += __shfl_xor_sync(0xffffffffu, q1, s);
        }
        if (lane < 4) {
            atomicAdd(&colsum[col], s0);
            atomicAdd(&colsum[col + 1], s1);
            atomicAdd(&colsq[col], q0);
            atomicAdd(&colsq[col + 1], q1);
        }
    }
    __syncthreads();
    if (tid < 128) {
        atomicAdd(&g_bn_sum[layer * D + tid], colsum[tid]);
        atomicAdd(&g_bn_sq[layer * D + tid], colsq[tid]);
    }
}

// ---------------- pool (with inlined BN finalize): h_l = relu(bn_l(buf)) -> pooled[l+1] ----------------
__global__ void pool_kernel(int layer, const int* __restrict__ graph_id,
                            const float* __restrict__ bn_g, const float* __restrict__ bn_b) {
    int t = threadIdx.x;
    int v0 = blockIdx.x * 128;
    const float* buf = (layer & 1) ? g_H : g_A;

    // every block computes the BN coefficients (cheap, redundant, no extra launch)
    float inv_n = 1.0f / (float)N_NODES;
    float mu  = g_bn_sum[layer * D + t] * inv_n;
    float var = g_bn_sq[layer * D + t] * inv_n - mu * mu;
    float inv = rsqrtf(var + 1e-5f);
    float a = inv * bn_g[layer * D + t];
    float c = bn_b[layer * D + t] - mu * a;
    if (blockIdx.x == 0) {              // persist for next layer's spmm
        g_bn_a[layer * D + t] = a;
        g_bn_c[layer * D + t] = c;
    }

    float* pool = g_pooled + (size_t)(layer + 1) * N_GRAPHS * D;
    float acc = 0.f;
    int gprev = graph_id[v0];
    for (int r = 0; r < 128; r++) {
        int v = v0 + r;
        if (v >= N_NODES) break;
        int g = graph_id[v];
        if (g != gprev) {
            atomicAdd(&pool[(size_t)gprev * D + t], acc);
            acc = 0.f;
            gprev = g;
        }
        float x = buf[(size_t)v * D + t];
        acc += fmaxf(fmaf(x, a, c), 0.f);
    }
    atomicAdd(&pool[(size_t)gprev * D + t], acc);
}

__global__ void pool_feat_kernel(const float* __restrict__ feat,
                                 const int* __restrict__ graph_id) {
    int t = threadIdx.x;
    int v0 = blockIdx.x * 128;
    float acc = 0.f;
    int gprev = graph_id[v0];
    for (int r = 0; r < 128; r++) {
        int v = v0 + r;
        if (v >= N_NODES) break;
        int g = graph_id[v];
        if (g != gprev) {
            atomicAdd(&g_pooled[(size_t)gprev * D + t], acc);
            acc = 0.f;
            gprev = g;
        }
        acc += feat[(size_t)v * D + t];
    }
    atomicAdd(&g_pooled[(size_t)gprev * D + t], acc);
}

// ---------------- head: score, log_softmax, mean_pooled ----------------
__global__ void head_kernel(const float* __restrict__ lin_w,
                            const float* __restrict__ lin_b,
                            float* __restrict__ out) {
    int g = blockIdx.x;
    int t = threadIdx.x;
    int lane = t & 31;
    __shared__ float red[OUTC];
    if (t < OUTC) red[t] = 0.f;
    __syncthreads();

    float p[NLAY + 1];
#pragma unroll
    for (int i = 0; i < NLAY + 1; i++)
        p[i] = g_pooled[(size_t)i * N_GRAPHS * D + (size_t)g * D + t];

    out[N_GRAPHS * OUTC + (size_t)g * D + t] =
        0.2f * (p[1] + p[2] + p[3] + p[4] + p[5]);

    float part[OUTC];
#pragma unroll
    for (int o = 0; o < OUTC; o++) part[o] = 0.f;
#pragma unroll
    for (int i = 0; i < NLAY + 1; i++) {
        const float* lw = lin_w + (size_t)i * D * OUTC + (size_t)t * OUTC;
#pragma unroll
        for (int o = 0; o < OUTC; o++) part[o] = fmaf(p[i], lw[o], part[o]);
    }
#pragma unroll
    for (int o = 0; o < OUTC; o++) {
        float v = part[o];
        for (int off = 16; off; off >>= 1) v += __shfl_down_sync(0xffffffffu, v, off);
        if (lane == 0) atomicAdd(&red[o], v);
    }
    __syncthreads();
    if (t == 0) {
        float s[OUTC];
        float mx = -1e30f;
        for (int o = 0; o < OUTC; o++) {
            float b = 0.f;
            for (int i = 0; i < NLAY + 1; i++) b += lin_b[i * OUTC + o];
            s[o] = red[o] + b;
            mx = fmaxf(mx, s[o]);
        }
        float lse = 0.f;
        for (int o = 0; o < OUTC; o++) lse += expf(s[o] - mx);
        lse = logf(lse) + mx;
        for (int o = 0; o < OUTC; o++) out[(size_t)g * OUTC + o] = s[o] - lse;
    }
}

// ---------------- launch ----------------
extern "C" void kernel_launch(void* const* d_in, const int* in_sizes, int n_in,
                              void* d_out, int out_size) {
    const float* feat     = (const float*)d_in[0];
    const int*   src      = (const int*)d_in[1];
    const int*   dst      = (const int*)d_in[2];
    const int*   graph_id = (const int*)d_in[3];
    const float* gcn_w    = (const float*)d_in[4];
    const float* gcn_b    = (const float*)d_in[5];
    const float* bn_g     = (const float*)d_in[6];
    const float* bn_b     = (const float*)d_in[7];
    const float* lin_w    = (const float*)d_in[8];
    const float* lin_b    = (const float*)d_in[9];
    float* out = (float*)d_out;

    cudaFuncSetAttribute(mma_gemm_kernel, cudaFuncAttributeMaxDynamicSharedMemorySize, SM_TOTAL);

    // launch order puts spmm(l=0) at position 6 so ncu (-s 5 -c 1) profiles it
    init_kernel<<<512, 256>>>(gcn_w);                                  // 1
    degree_kernel<<<(N_EDGES + 255) / 256, 256>>>(src, dst);           // 2
    scan_partial_kernel<<<SCAN_BLKS, 512>>>();                         // 3 (+ norms)
    scan_write_kernel<<<SCAN_BLKS, 512>>>();                           // 4 (inlined offsets)
    fill_kernel<<<(N_EDGES + 255) / 256, 256>>>(src, dst);             // 5

    int spmm_blocks = (N_NODES * 32 + 255) / 256;
    int row_blocks  = (N_NODES + 127) / 128;
    for (int l = 0; l < NLAY; l++) {
        spmm_kernel<<<spmm_blocks, 256>>>(l, feat);                    // 6 on l=0
        mma_gemm_kernel<<<row_blocks, 256, SM_TOTAL>>>(l, gcn_b);
        pool_kernel<<<row_blocks, 128>>>(l, graph_id, bn_g, bn_b);
    }
    pool_feat_kernel<<<(N_NODES + 127) / 128, 128>>>(feat, graph_id);  // independent; moved late
    head_kernel<<<N_GRAPHS, 128>>>(lin_w, lin_b, out);
}

// round 15
// speedup vs baseline: 1.6658x; 1.0031x over previous
#include <cuda_runtime.h>
#include <cuda_bf16.h>
#include <math.h>
#include <stdint.h>

#define N_NODES 100000
#define N_EDGES 600000
#define D       128
#define OUTC    10
#define NLAY    5
#define N_GRAPHS 200
#define SCAN_BLKS 196   // ceil(100000/512)

// ---------------- device scratch (no allocations allowed) ----------------
// NOTE: all arrays that must be zero at call entry are zeroed by tail_zero_kernel
// at the END of each call (and are statically zero-initialized for the first call).
__device__ __align__(128) float g_A[(size_t)N_NODES * D];
__device__ __align__(128) float g_H[(size_t)N_NODES * D];
__device__ int   g_deg_out[N_NODES];      // zeroed by tail
__device__ int   g_deg_in[N_NODES];       // zeroed by tail
__device__ float g_norm_out[N_NODES];
__device__ float g_norm_in[N_NODES];
__device__ int   g_row_ptr[N_NODES + 1];
__device__ int   g_cursor[N_NODES];
__device__ int   g_csr_src[N_EDGES];
__device__ volatile unsigned long long g_scan_status[SCAN_BLKS];  // zeroed by tail
__device__ __nv_bfloat16 g_Bh[NLAY * D * D];   // W transposed [l][n][k], bf16
__device__ float g_pooled[(NLAY + 1) * N_GRAPHS * D];  // zeroed by tail
__device__ float g_bn_sum[NLAY * D];      // zeroed by tail
__device__ float g_bn_sq[NLAY * D];       // zeroed by tail
__device__ float g_bn_a[NLAY * D];
__device__ float g_bn_c[NLAY * D];

__device__ __forceinline__ uint32_t smem_u32(const void* p) {
    uint32_t a;
    asm("{ .reg .u64 t; cvta.to.shared.u64 t, %1; cvt.u32.u64 %0, t; }" : "=r"(a) : "l"(p));
    return a;
}

// ---------------- degrees (arrays are pre-zeroed by prior call / static init) ----------------
__global__ void degree_kernel(const int* __restrict__ src, const int* __restrict__ dst) {
    int e = blockIdx.x * blockDim.x + threadIdx.x;
    if (e < N_EDGES) {
        atomicAdd(&g_deg_out[src[e]], 1);
        atomicAdd(&g_deg_in[dst[e]], 1);
    }
}

// ---------------- single-pass scan (decoupled lookback) + norms ----------------
__global__ void __launch_bounds__(512) scan_kernel() {
    __shared__ int sa[512], sb[512];
    __shared__ int s_prefix;
    int t = threadIdx.x, bid = blockIdx.x;
    int gi = bid * 512 + t;
    int din = 0;
    if (gi < N_NODES) {
        int dout = g_deg_out[gi];
        din = g_deg_in[gi];
        g_norm_out[gi] = rsqrtf((float)max(dout, 1));
        g_norm_in[gi]  = rsqrtf((float)max(din, 1));
    }
    sa[t] = din;
    __syncthreads();
    int* in = sa; int* ot = sb;
    for (int off = 1; off < 512; off <<= 1) {
        ot[t] = in[t] + ((t >= off) ? in[t - off] : 0);
        __syncthreads();
        int* tmp = in; in = ot; ot = tmp;
    }
    int incl = in[t];
    int aggregate = in[511];

    if (t == 0) {
        if (bid == 0) {
            __threadfence();
            g_scan_status[0] = (2ULL << 32) | (unsigned)aggregate;
            s_prefix = 0;
        } else {
            __threadfence();
            g_scan_status[bid] = (1ULL << 32) | (unsigned)aggregate;
            long long ex = 0;
            int idx = bid - 1;
            while (true) {
                unsigned long long st = g_scan_status[idx];
                unsigned flag = (unsigned)(st >> 32);
                if (flag == 0) continue;          // not yet published; spin
                ex += (unsigned)st;
                if (flag == 2) break;             // found a full prefix
                idx--;
            }
            __threadfence();
            g_scan_status[bid] = (2ULL << 32) | (unsigned)(ex + aggregate);
            s_prefix = (int)ex;
        }
    }
    __syncthreads();
    int base = s_prefix;
    if (gi < N_NODES) {
        int ex = base + incl - din;
        g_row_ptr[gi] = ex;
        g_cursor[gi]  = ex;
    }
    if (gi == N_NODES - 1) g_row_ptr[N_NODES] = base + incl;
}

__global__ void fill_kernel(const int* __restrict__ src, const int* __restrict__ dst) {
    int e = blockIdx.x * blockDim.x + threadIdx.x;
    if (e < N_EDGES) {
        int pos = atomicAdd(&g_cursor[dst[e]], 1);
        g_csr_src[pos] = src[e];
    }
}

// ---------------- one-time W conversion (off the critical path: after spmm l0) ----------------
__global__ void wcvt_kernel(const float* __restrict__ gcn_w) {
    int idx = blockIdx.x * blockDim.x + threadIdx.x;
    int stride = gridDim.x * blockDim.x;
    for (int i = idx; i < NLAY * D * D; i += stride) {
        int l = i / (D * D);
        int kn = i % (D * D);
        int k = kn / D, n = kn % D;
        g_Bh[(size_t)l * D * D + (size_t)n * D + k] = __float2bfloat16_rn(gcn_w[i]);
    }
}

// ---------------- tail: restore zeroed state for the next call ----------------
__global__ void tail_zero_kernel() {
    int idx = blockIdx.x * blockDim.x + threadIdx.x;
    int stride = gridDim.x * blockDim.x;
    for (int i = idx; i < N_NODES; i += stride) { g_deg_out[i] = 0; g_deg_in[i] = 0; }
    for (int i = idx; i < (NLAY + 1) * N_GRAPHS * D; i += stride) g_pooled[i] = 0.f;
    for (int i = idx; i < NLAY * D; i += stride) { g_bn_sum[i] = 0.f; g_bn_sq[i] = 0.f; }
    for (int i = idx; i < SCAN_BLKS; i += stride) g_scan_status[i] = 0ULL;
}

// ---------------- SpMM + on-the-fly BN/ReLU + residual: warp per node ----------------
// layer 0: hin = feat, used RAW. layer l>0: h = relu(a*x + c) with coeffs of layer l-1.
// Inner loop software-pipelined depth 1 (verified R11 structure).
__global__ void spmm_kernel(int layer, const float* __restrict__ feat) {
    int gtid = blockIdx.x * blockDim.x + threadIdx.x;
    int w = gtid >> 5;
    int lane = gtid & 31;
    if (w >= N_NODES) return;
    const float* hin = (layer == 0) ? feat : ((layer & 1) ? g_A : g_H);
    float* outp = (layer & 1) ? g_H : g_A;
    const float4* h4 = (const float4*)hin;
    const bool dorelu = (layer > 0);

    float4 a4 = make_float4(1.f, 1.f, 1.f, 1.f);
    float4 c4 = make_float4(0.f, 0.f, 0.f, 0.f);
    if (dorelu) {
        a4 = ((const float4*)(g_bn_a + (size_t)(layer - 1) * D))[lane];
        c4 = ((const float4*)(g_bn_c + (size_t)(layer - 1) * D))[lane];
    }

    int start = g_row_ptr[w];
    int end   = g_row_ptr[w + 1];
    float4 acc = make_float4(0.f, 0.f, 0.f, 0.f);
    for (int base = start; base < end; base += 32) {
        int n = min(32, end - base);
        int s = 0; float ns = 0.f;
        if (lane < n) {
            s = g_csr_src[base + lane];
            ns = g_norm_out[s];
        }
        int   sj = __shfl_sync(0xffffffffu, s, 0);
        float nj = __shfl_sync(0xffffffffu, ns, 0);
        float4 x = h4[(size_t)sj * 32 + lane];
        for (int j = 0; j < n; j++) {
            float nj1 = 0.f;
            float4 x1 = make_float4(0.f, 0.f, 0.f, 0.f);
            if (j + 1 < n) {
                int sj1 = __shfl_sync(0xffffffffu, s, j + 1);
                nj1 = __shfl_sync(0xffffffffu, ns, j + 1);
                x1 = h4[(size_t)sj1 * 32 + lane];
            }
            float hx = fmaf(x.x, a4.x, c4.x);
            float hy = fmaf(x.y, a4.y, c4.y);
            float hz = fmaf(x.z, a4.z, c4.z);
            float hw = fmaf(x.w, a4.w, c4.w);
            if (dorelu) {
                hx = fmaxf(hx, 0.f); hy = fmaxf(hy, 0.f);
                hz = fmaxf(hz, 0.f); hw = fmaxf(hw, 0.f);
            }
            acc.x = fmaf(hx, nj, acc.x);
            acc.y = fmaf(hy, nj, acc.y);
            acc.z = fmaf(hz, nj, acc.z);
            acc.w = fmaf(hw, nj, acc.w);
            x = x1; nj = nj1;
        }
    }
    float c = 0.9f * g_norm_in[w];
    float4 xv = h4[(size_t)w * 32 + lane];
    float4 hv;
    hv.x = fmaf(xv.x, a4.x, c4.x);
    hv.y = fmaf(xv.y, a4.y, c4.y);
    hv.z = fmaf(xv.z, a4.z, c4.z);
    hv.w = fmaf(xv.w, a4.w, c4.w);
    if (dorelu) {
        hv.x = fmaxf(hv.x, 0.f); hv.y = fmaxf(hv.y, 0.f);
        hv.z = fmaxf(hv.z, 0.f); hv.w = fmaxf(hv.w, 0.f);
    }
    float4 r;
    r.x = c * acc.x + 0.1f * hv.x;
    r.y = c * acc.y + 0.1f * hv.y;
    r.z = c * acc.z + 0.1f * hv.z;
    r.w = c * acc.w + 0.1f * hv.w;
    ((float4*)outp)[(size_t)w * 32 + lane] = r;
}

// ======== GEMM: buf = (1-beta)*buf + beta*(buf@W) + bias, single bf16 MMA, exact identity ========
// smem layout (bytes)
#define SM_AHI    0
#define SM_WHI    32768
#define SM_BIAS   65536
#define SM_COLSUM 66048
#define SM_COLSQ  66560
#define SM_TOTAL  67072

// swizzled offset inside a 128x128-bf16 tile: row-major 256B rows, 16B chunks XOR row&7
__device__ __forceinline__ uint32_t sw_off(int row, int chunk) {
    return (uint32_t)(row * 256 + ((chunk ^ (row & 7)) << 4));
}

__device__ __forceinline__ void ldsm_x4(uint32_t addr, uint32_t& r0, uint32_t& r1,
                                        uint32_t& r2, uint32_t& r3) {
    asm volatile("ldmatrix.sync.aligned.m8n8.x4.shared.b16 {%0,%1,%2,%3}, [%4];"
                 : "=r"(r0), "=r"(r1), "=r"(r2), "=r"(r3) : "r"(addr));
}

__device__ __forceinline__ void mma_bf16(float* d, uint32_t a0, uint32_t a1, uint32_t a2,
                                         uint32_t a3, uint32_t b0, uint32_t b1) {
    asm volatile(
        "mma.sync.aligned.m16n8k16.row.col.f32.bf16.bf16.f32 "
        "{%0,%1,%2,%3}, {%4,%5,%6,%7}, {%8,%9}, {%0,%1,%2,%3};"
        : "+f"(d[0]), "+f"(d[1]), "+f"(d[2]), "+f"(d[3])
        : "r"(a0), "r"(a1), "r"(a2), "r"(a3), "r"(b0), "r"(b1));
}

__global__ void __launch_bounds__(256, 2) mma_gemm_kernel(int layer, const float* __restrict__ gcn_b) {
    extern __shared__ char smem[];
    uint32_t sb = smem_u32(smem);
    int tid = threadIdx.x;
    int wid = tid >> 5, lane = tid & 31;
    int r0 = blockIdx.x * 128;
    float* buf = (layer & 1) ? g_H : g_A;
    const float BETA = (float)log1p(1.0 / (double)D);
    const float OMB  = 1.0f - BETA;

    if (tid < 128) {
        ((float*)(smem + SM_COLSUM))[tid] = 0.f;
        ((float*)(smem + SM_COLSQ))[tid]  = 0.f;
        ((float*)(smem + SM_BIAS))[tid]   = gcn_b[layer * D + tid];
    }

    // ---- stage W ([n][k] bf16) into swizzled smem ----
    {
        const uint4* Bh = (const uint4*)(g_Bh + (size_t)layer * D * D);
#pragma unroll
        for (int i = 0; i < 8; i++) {
            int u = tid + i * 256;
            int n = u >> 4;
            int c = u & 15;
            *(uint4*)(smem + SM_WHI + sw_off(n, c)) = Bh[u];
        }
    }
    // ---- stage A tile (fp32 -> bf16, packed cvt) into swizzled smem ----
    {
        const float4* A4 = (const float4*)buf;
#pragma unroll
        for (int i = 0; i < 16; i++) {
            int j = tid + i * 256;
            int m = j >> 5;
            int k4 = j & 31;
            int row = r0 + m;
            float4 x = (row < N_NODES) ? A4[(size_t)row * 32 + k4]
                                       : make_float4(0.f, 0.f, 0.f, 0.f);
            __nv_bfloat162 h01 = __float22bfloat162_rn(make_float2(x.x, x.y));
            __nv_bfloat162 h23 = __float22bfloat162_rn(make_float2(x.z, x.w));
            uint32_t off = sw_off(m, k4 >> 1) + (uint32_t)((k4 & 1) << 3);
            __nv_bfloat162* ph = (__nv_bfloat162*)(smem + SM_AHI + off);
            ph[0] = h01;
            ph[1] = h23;
        }
    }
    __syncthreads();

    int m0 = (wid & 3) * 32;
    int n0 = (wid >> 2) * 64;

    float acc[2][8][4];
#pragma unroll
    for (int mt = 0; mt < 2; mt++)
#pragma unroll
        for (int nt = 0; nt < 8; nt++)
#pragma unroll
            for (int q = 0; q < 4; q++) acc[mt][nt][q] = 0.f;

    int lr = lane & 7;
    int lm = lane >> 3;

#pragma unroll
    for (int kk = 0; kk < 8; kk++) {
        uint32_t ahi[2][4];
#pragma unroll
        for (int mt = 0; mt < 2; mt++) {
            int arow = m0 + mt * 16 + (lm & 1) * 8 + lr;
            int achk = kk * 2 + (lm >> 1);
            ldsm_x4(sb + SM_AHI + sw_off(arow, achk),
                    ahi[mt][0], ahi[mt][1], ahi[mt][2], ahi[mt][3]);
        }
        uint32_t bhi[8][2];
#pragma unroll
        for (int jp = 0; jp < 4; jp++) {
            int brow = n0 + jp * 16 + (lm >> 1) * 8 + lr;
            int bchk = kk * 2 + (lm & 1);
            ldsm_x4(sb + SM_WHI + sw_off(brow, bchk),
                    bhi[jp * 2][0], bhi[jp * 2][1], bhi[jp * 2 + 1][0], bhi[jp * 2 + 1][1]);
        }
#pragma unroll
        for (int mt = 0; mt < 2; mt++)
#pragma unroll
            for (int nt = 0; nt < 8; nt++)
                mma_bf16(acc[mt][nt], ahi[mt][0], ahi[mt][1], ahi[mt][2], ahi[mt][3],
                         bhi[nt][0], bhi[nt][1]);
    }

    float* bias = (float*)(smem + SM_BIAS);
    float* colsum = (float*)(smem + SM_COLSUM);
    float* colsq  = (float*)(smem + SM_COLSQ);
    int rl = lane >> 2;
    int cl = (lane & 3) * 2;

#pragma unroll
    for (int nt = 0; nt < 8; nt++) {
        int col = n0 + nt * 8 + cl;
        float b0v = bias[col], b1v = bias[col + 1];
        float s0 = 0.f, s1 = 0.f, q0 = 0.f, q1 = 0.f;
#pragma unroll
        for (int mt = 0; mt < 2; mt++) {
            int rlo = r0 + m0 + mt * 16 + rl;
            int rhi = rlo + 8;
            if (rlo < N_NODES) {
                float2 ga = *(const float2*)&buf[(size_t)rlo * D + col];
                float c0 = fmaf(BETA, acc[mt][nt][0], fmaf(OMB, ga.x, b0v));
                float c1 = fmaf(BETA, acc[mt][nt][1], fmaf(OMB, ga.y, b1v));
                *(float2*)&buf[(size_t)rlo * D + col] = make_float2(c0, c1);
                s0 += c0; s1 += c1;
                q0 = fmaf(c0, c0, q0); q1 = fmaf(c1, c1, q1);
            }
            if (rhi < N_NODES) {
                float2 ga = *(const float2*)&buf[(size_t)rhi * D + col];
                float c2 = fmaf(BETA, acc[mt][nt][2], fmaf(OMB, ga.x, b0v));
                float c3 = fmaf(BETA, acc[mt][nt][3], fmaf(OMB, ga.y, b1v));
                *(float2*)&buf[(size_t)rhi * D + col] = make_float2(c2, c3);
                s0 += c2; s1 += c3;
                q0 = fmaf(c2, c2, q0); q1 = fmaf(c3, c3, q1);
            }
        }
#pragma unroll
        for (int s = 4; s < 32; s <<= 1) {
            s0 += __shfl_xor_sync(0xffffffffu, s0, s);
            s1 += __shfl_xor_sync(0xffffffffu, s1, s);
            q0 += __shfl_xor_sync(0xffffffffu, q0, s);
            q1 += __shfl_xor_sync(0xffffffffu, q1, s);
        }
        if (lane < 4) {
            atomicAdd(&colsum[col], s0);
            atomicAdd(&colsum[col + 1], s1);
            atomicAdd(&colsq[col], q0);
            atomicAdd(&colsq[col + 1], q1);
        }
    }
    __syncthreads();
    if (tid < 128) {
        atomicAdd(&g_bn_sum[layer * D + tid], colsum[tid]);
        atomicAdd(&g_bn_sq[layer * D + tid], colsq[tid]);
    }
}

// ---------------- pool (with inlined BN finalize): h_l = relu(bn_l(buf)) -> pooled[l+1] ----------------
__global__ void pool_kernel(int layer, const int* __restrict__ graph_id,
                            const float* __restrict__ bn_g, const float* __restrict__ bn_b) {
    int t = threadIdx.x;
    int v0 = blockIdx.x * 128;
    const float* buf = (layer & 1) ? g_H : g_A;

    float inv_n = 1.0f / (float)N_NODES;
    float mu  = g_bn_sum[layer * D + t] * inv_n;
    float var = g_bn_sq[layer * D + t] * inv_n - mu * mu;
    float inv = rsqrtf(var + 1e-5f);
    float a = inv * bn_g[layer * D + t];
    float c = bn_b[layer * D + t] - mu * a;
    if (blockIdx.x == 0) {
        g_bn_a[layer * D + t] = a;
        g_bn_c[layer * D + t] = c;
    }

    float* pool = g_pooled + (size_t)(layer + 1) * N_GRAPHS * D;
    float acc = 0.f;
    int gprev = graph_id[v0];
    for (int r = 0; r < 128; r++) {
        int v = v0 + r;
        if (v >= N_NODES) break;
        int g = graph_id[v];
        if (g != gprev) {
            atomicAdd(&pool[(size_t)gprev * D + t], acc);
            acc = 0.f;
            gprev = g;
        }
        float x = buf[(size_t)v * D + t];
        acc += fmaxf(fmaf(x, a, c), 0.f);
    }
    atomicAdd(&pool[(size_t)gprev * D + t], acc);
}

__global__ void pool_feat_kernel(const float* __restrict__ feat,
                                 const int* __restrict__ graph_id) {
    int t = threadIdx.x;
    int v0 = blockIdx.x * 128;
    float acc = 0.f;
    int gprev = graph_id[v0];
    for (int r = 0; r < 128; r++) {
        int v = v0 + r;
        if (v >= N_NODES) break;
        int g = graph_id[v];
        if (g != gprev) {
            atomicAdd(&g_pooled[(size_t)gprev * D + t], acc);
            acc = 0.f;
            gprev = g;
        }
        acc += feat[(size_t)v * D + t];
    }
    atomicAdd(&g_pooled[(size_t)gprev * D + t], acc);
}

// ---------------- head: score, log_softmax, mean_pooled ----------------
__global__ void head_kernel(const float* __restrict__ lin_w,
                            const float* __restrict__ lin_b,
                            float* __restrict__ out) {
    int g = blockIdx.x;
    int t = threadIdx.x;
    int lane = t & 31;
    __shared__ float red[OUTC];
    if (t < OUTC) red[t] = 0.f;
    __syncthreads();

    float p[NLAY + 1];
#pragma unroll
    for (int i = 0; i < NLAY + 1; i++)
        p[i] = g_pooled[(size_t)i * N_GRAPHS * D + (size_t)g * D + t];

    out[N_GRAPHS * OUTC + (size_t)g * D + t] =
        0.2f * (p[1] + p[2] + p[3] + p[4] + p[5]);

    float part[OUTC];
#pragma unroll
    for (int o = 0; o < OUTC; o++) part[o] = 0.f;
#pragma unroll
    for (int i = 0; i < NLAY + 1; i++) {
        const float* lw = lin_w + (size_t)i * D * OUTC + (size_t)t * OUTC;
#pragma unroll
        for (int o = 0; o < OUTC; o++) part[o] = fmaf(p[i], lw[o], part[o]);
    }
#pragma unroll
    for (int o = 0; o < OUTC; o++) {
        float v = part[o];
        for (int off = 16; off; off >>= 1) v += __shfl_down_sync(0xffffffffu, v, off);
        if (lane == 0) atomicAdd(&red[o], v);
    }
    __syncthreads();
    if (t == 0) {
        float s[OUTC];
        float mx = -1e30f;
        for (int o = 0; o < OUTC; o++) {
            float b = 0.f;
            for (int i = 0; i < NLAY + 1; i++) b += lin_b[i * OUTC + o];
            s[o] = red[o] + b;
            mx = fmaxf(mx, s[o]);
        }
        float lse = 0.f;
        for (int o = 0; o < OUTC; o++) lse += expf(s[o] - mx);
        lse = logf(lse) + mx;
        for (int o = 0; o < OUTC; o++) out[(size_t)g * OUTC + o] = s[o] - lse;
    }
}

// ---------------- launch ----------------
extern "C" void kernel_launch(void* const* d_in, const int* in_sizes, int n_in,
                              void* d_out, int out_size) {
    const float* feat     = (const float*)d_in[0];
    const int*   src      = (const int*)d_in[1];
    const int*   dst      = (const int*)d_in[2];
    const int*   graph_id = (const int*)d_in[3];
    const float* gcn_w    = (const float*)d_in[4];
    const float* gcn_b    = (const float*)d_in[5];
    const float* bn_g     = (const float*)d_in[6];
    const float* bn_b     = (const float*)d_in[7];
    const float* lin_w    = (const float*)d_in[8];
    const float* lin_b    = (const float*)d_in[9];
    float* out = (float*)d_out;

    cudaFuncSetAttribute(mma_gemm_kernel, cudaFuncAttributeMaxDynamicSharedMemorySize, SM_TOTAL);

    int spmm_blocks = (N_NODES * 32 + 255) / 256;
    int row_blocks  = (N_NODES + 127) / 128;

    degree_kernel<<<(N_EDGES + 255) / 256, 256>>>(src, dst);   // 1
    scan_kernel<<<SCAN_BLKS, 512>>>();                         // 2 (lookback scan + norms)
    fill_kernel<<<(N_EDGES + 255) / 256, 256>>>(src, dst);     // 3
    spmm_kernel<<<spmm_blocks, 256>>>(0, feat);                // 4 <- profiled by ncu
    wcvt_kernel<<<256, 256>>>(gcn_w);                          // 5 (one-time W cvt, before gemm)

    for (int l = 0; l < NLAY; l++) {
        if (l > 0) spmm_kernel<<<spmm_blocks, 256>>>(l, feat);
        mma_gemm_kernel<<<row_blocks, 256, SM_TOTAL>>>(l, gcn_b);
        pool_kernel<<<row_blocks, 128>>>(l, graph_id, bn_g, bn_b);
    }
    pool_feat_kernel<<<(N_NODES + 127) / 128, 128>>>(feat, graph_id);
    head_kernel<<<N_GRAPHS, 128>>>(lin_w, lin_b, out);
    tail_zero_kernel<<<512, 256>>>();   // restore zeroed state for next call
}

// round 16
// speedup vs baseline: 1.7424x; 1.0460x over previous
#include <cuda_runtime.h>
#include <cuda_bf16.h>
#include <math.h>
#include <stdint.h>

#define N_NODES 100000
#define N_EDGES 600000
#define D       128
#define OUTC    10
#define NLAY    5
#define N_GRAPHS 200
#define SCAN_BLKS 196   // ceil(100000/512)

// ---------------- device scratch (no allocations allowed) ----------------
// Arrays that must be zero at call entry are zeroed by tail_zero_kernel at the
// END of each call (statically zero-initialized for the first call).
__device__ __align__(128) float g_A[(size_t)N_NODES * D];
__device__ __align__(128) float g_H[(size_t)N_NODES * D];
__device__ int   g_deg_out[N_NODES];      // zeroed by tail
__device__ int   g_deg_in[N_NODES];       // zeroed by tail
__device__ float g_norm_out[N_NODES];
__device__ float g_norm_in[N_NODES];
__device__ int   g_row_ptr[N_NODES + 1];
__device__ int   g_cursor[N_NODES];
__device__ int   g_csr_src[N_EDGES];
__device__ volatile unsigned long long g_scan_status[SCAN_BLKS];  // zeroed by tail
__device__ int   g_gcount[N_GRAPHS];      // zeroed by tail
__device__ int   g_gstart[N_GRAPHS + 1];
__device__ __nv_bfloat16 g_Bh[NLAY * D * D];   // W transposed [l][n][k], bf16
__device__ float g_pooled[(NLAY + 1) * N_GRAPHS * D];  // zeroed by tail
__device__ float g_bn_sum[NLAY * D];      // zeroed by tail
__device__ float g_bn_sq[NLAY * D];       // zeroed by tail
__device__ float g_bn_a[NLAY * D];
__device__ float g_bn_c[NLAY * D];

__device__ __forceinline__ uint32_t smem_u32(const void* p) {
    uint32_t a;
    asm("{ .reg .u64 t; cvta.to.shared.u64 t, %1; cvt.u32.u64 %0, t; }" : "=r"(a) : "l"(p));
    return a;
}

// ---------------- degrees ----------------
__global__ void degree_kernel(const int* __restrict__ src, const int* __restrict__ dst) {
    int e = blockIdx.x * blockDim.x + threadIdx.x;
    if (e < N_EDGES) {
        atomicAdd(&g_deg_out[src[e]], 1);
        atomicAdd(&g_deg_in[dst[e]], 1);
    }
}

// ---------------- single-pass scan (decoupled lookback) + norms ----------------
__global__ void __launch_bounds__(512) scan_kernel() {
    __shared__ int sa[512], sb[512];
    __shared__ int s_prefix;
    int t = threadIdx.x, bid = blockIdx.x;
    int gi = bid * 512 + t;
    int din = 0;
    if (gi < N_NODES) {
        int dout = g_deg_out[gi];
        din = g_deg_in[gi];
        g_norm_out[gi] = rsqrtf((float)max(dout, 1));
        g_norm_in[gi]  = rsqrtf((float)max(din, 1));
    }
    sa[t] = din;
    __syncthreads();
    int* in = sa; int* ot = sb;
    for (int off = 1; off < 512; off <<= 1) {
        ot[t] = in[t] + ((t >= off) ? in[t - off] : 0);
        __syncthreads();
        int* tmp = in; in = ot; ot = tmp;
    }
    int incl = in[t];
    int aggregate = in[511];

    if (t == 0) {
        if (bid == 0) {
            __threadfence();
            g_scan_status[0] = (2ULL << 32) | (unsigned)aggregate;
            s_prefix = 0;
        } else {
            __threadfence();
            g_scan_status[bid] = (1ULL << 32) | (unsigned)aggregate;
            long long ex = 0;
            int idx = bid - 1;
            while (true) {
                unsigned long long st = g_scan_status[idx];
                unsigned flag = (unsigned)(st >> 32);
                if (flag == 0) continue;
                ex += (unsigned)st;
                if (flag == 2) break;
                idx--;
            }
            __threadfence();
            g_scan_status[bid] = (2ULL << 32) | (unsigned)(ex + aggregate);
            s_prefix = (int)ex;
        }
    }
    __syncthreads();
    int base = s_prefix;
    if (gi < N_NODES) {
        int ex = base + incl - din;
        g_row_ptr[gi] = ex;
        g_cursor[gi]  = ex;
    }
    if (gi == N_NODES - 1) g_row_ptr[N_NODES] = base + incl;
}

__global__ void fill_kernel(const int* __restrict__ src, const int* __restrict__ dst) {
    int e = blockIdx.x * blockDim.x + threadIdx.x;
    if (e < N_EDGES) {
        int pos = atomicAdd(&g_cursor[dst[e]], 1);
        g_csr_src[pos] = src[e];
    }
}

// ---------------- one-time W conversion ----------------
__global__ void wcvt_kernel(const float* __restrict__ gcn_w) {
    int idx = blockIdx.x * blockDim.x + threadIdx.x;
    int stride = gridDim.x * blockDim.x;
    for (int i = idx; i < NLAY * D * D; i += stride) {
        int l = i / (D * D);
        int kn = i % (D * D);
        int k = kn / D, n = kn % D;
        g_Bh[(size_t)l * D * D + (size_t)n * D + k] = __float2bfloat16_rn(gcn_w[i]);
    }
}

// ---------------- graph ranges: histogram + 1-block scan ----------------
__global__ void gcount_kernel(const int* __restrict__ graph_id) {
    int v = blockIdx.x * blockDim.x + threadIdx.x;
    if (v < N_NODES) atomicAdd(&g_gcount[graph_id[v]], 1);
}

__global__ void gscan_kernel() {
    __shared__ int sa[256], sb[256];
    int t = threadIdx.x;
    int v = (t < N_GRAPHS) ? g_gcount[t] : 0;
    sa[t] = v;
    __syncthreads();
    int* in = sa; int* ot = sb;
    for (int off = 1; off < 256; off <<= 1) {
        ot[t] = in[t] + ((t >= off) ? in[t - off] : 0);
        __syncthreads();
        int* tmp = in; in = ot; ot = tmp;
    }
    if (t < N_GRAPHS) g_gstart[t] = in[t] - v;           // exclusive
    if (t == N_GRAPHS - 1) g_gstart[N_GRAPHS] = in[t];
}

// ---------------- tail: restore zeroed state for the next call ----------------
__global__ void tail_zero_kernel() {
    int idx = blockIdx.x * blockDim.x + threadIdx.x;
    int stride = gridDim.x * blockDim.x;
    for (int i = idx; i < N_NODES; i += stride) { g_deg_out[i] = 0; g_deg_in[i] = 0; }
    for (int i = idx; i < (NLAY + 1) * N_GRAPHS * D; i += stride) g_pooled[i] = 0.f;
    for (int i = idx; i < NLAY * D; i += stride) { g_bn_sum[i] = 0.f; g_bn_sq[i] = 0.f; }
    for (int i = idx; i < SCAN_BLKS; i += stride) g_scan_status[i] = 0ULL;
    for (int i = idx; i < N_GRAPHS; i += stride) g_gcount[i] = 0;
}

// ---------------- SpMM + on-the-fly BN/ReLU + residual: warp per node ----------------
__global__ void spmm_kernel(int layer, const float* __restrict__ feat) {
    int gtid = blockIdx.x * blockDim.x + threadIdx.x;
    int w = gtid >> 5;
    int lane = gtid & 31;
    if (w >= N_NODES) return;
    const float* hin = (layer == 0) ? feat : ((layer & 1) ? g_A : g_H);
    float* outp = (layer & 1) ? g_H : g_A;
    const float4* h4 = (const float4*)hin;
    const bool dorelu = (layer > 0);

    float4 a4 = make_float4(1.f, 1.f, 1.f, 1.f);
    float4 c4 = make_float4(0.f, 0.f, 0.f, 0.f);
    if (dorelu) {
        a4 = ((const float4*)(g_bn_a + (size_t)(layer - 1) * D))[lane];
        c4 = ((const float4*)(g_bn_c + (size_t)(layer - 1) * D))[lane];
    }

    int start = g_row_ptr[w];
    int end   = g_row_ptr[w + 1];
    float4 acc = make_float4(0.f, 0.f, 0.f, 0.f);
    for (int base = start; base < end; base += 32) {
        int n = min(32, end - base);
        int s = 0; float ns = 0.f;
        if (lane < n) {
            s = g_csr_src[base + lane];
            ns = g_norm_out[s];
        }
        int   sj = __shfl_sync(0xffffffffu, s, 0);
        float nj = __shfl_sync(0xffffffffu, ns, 0);
        float4 x = h4[(size_t)sj * 32 + lane];
        for (int j = 0; j < n; j++) {
            float nj1 = 0.f;
            float4 x1 = make_float4(0.f, 0.f, 0.f, 0.f);
            if (j + 1 < n) {
                int sj1 = __shfl_sync(0xffffffffu, s, j + 1);
                nj1 = __shfl_sync(0xffffffffu, ns, j + 1);
                x1 = h4[(size_t)sj1 * 32 + lane];
            }
            float hx = fmaf(x.x, a4.x, c4.x);
            float hy = fmaf(x.y, a4.y, c4.y);
            float hz = fmaf(x.z, a4.z, c4.z);
            float hw = fmaf(x.w, a4.w, c4.w);
            if (dorelu) {
                hx = fmaxf(hx, 0.f); hy = fmaxf(hy, 0.f);
                hz = fmaxf(hz, 0.f); hw = fmaxf(hw, 0.f);
            }
            acc.x = fmaf(hx, nj, acc.x);
            acc.y = fmaf(hy, nj, acc.y);
            acc.z = fmaf(hz, nj, acc.z);
            acc.w = fmaf(hw, nj, acc.w);
            x = x1; nj = nj1;
        }
    }
    float c = 0.9f * g_norm_in[w];
    float4 xv = h4[(size_t)w * 32 + lane];
    float4 hv;
    hv.x = fmaf(xv.x, a4.x, c4.x);
    hv.y = fmaf(xv.y, a4.y, c4.y);
    hv.z = fmaf(xv.z, a4.z, c4.z);
    hv.w = fmaf(xv.w, a4.w, c4.w);
    if (dorelu) {
        hv.x = fmaxf(hv.x, 0.f); hv.y = fmaxf(hv.y, 0.f);
        hv.z = fmaxf(hv.z, 0.f); hv.w = fmaxf(hv.w, 0.f);
    }
    float4 r;
    r.x = c * acc.x + 0.1f * hv.x;
    r.y = c * acc.y + 0.1f * hv.y;
    r.z = c * acc.z + 0.1f * hv.z;
    r.w = c * acc.w + 0.1f * hv.w;
    ((float4*)outp)[(size_t)w * 32 + lane] = r;
}

// ======== GEMM: buf = (1-beta)*buf + beta*(buf@W) + bias, single bf16 MMA, exact identity ========
#define SM_AHI    0
#define SM_WHI    32768
#define SM_BIAS   65536
#define SM_COLSUM 66048
#define SM_COLSQ  66560
#define SM_TOTAL  67072

__device__ __forceinline__ uint32_t sw_off(int row, int chunk) {
    return (uint32_t)(row * 256 + ((chunk ^ (row & 7)) << 4));
}

__device__ __forceinline__ void ldsm_x4(uint32_t addr, uint32_t& r0, uint32_t& r1,
                                        uint32_t& r2, uint32_t& r3) {
    asm volatile("ldmatrix.sync.aligned.m8n8.x4.shared.b16 {%0,%1,%2,%3}, [%4];"
                 : "=r"(r0), "=r"(r1), "=r"(r2), "=r"(r3) : "r"(addr));
}

__device__ __forceinline__ void mma_bf16(float* d, uint32_t a0, uint32_t a1, uint32_t a2,
                                         uint32_t a3, uint32_t b0, uint32_t b1) {
    asm volatile(
        "mma.sync.aligned.m16n8k16.row.col.f32.bf16.bf16.f32 "
        "{%0,%1,%2,%3}, {%4,%5,%6,%7}, {%8,%9}, {%0,%1,%2,%3};"
        : "+f"(d[0]), "+f"(d[1]), "+f"(d[2]), "+f"(d[3])
        : "r"(a0), "r"(a1), "r"(a2), "r"(a3), "r"(b0), "r"(b1));
}

__global__ void __launch_bounds__(256, 2) mma_gemm_kernel(int layer, const float* __restrict__ gcn_b) {
    extern __shared__ char smem[];
    uint32_t sb = smem_u32(smem);
    int tid = threadIdx.x;
    int wid = tid >> 5, lane = tid & 31;
    int r0 = blockIdx.x * 128;
    float* buf = (layer & 1) ? g_H : g_A;
    const float BETA = (float)log1p(1.0 / (double)D);
    const float OMB  = 1.0f - BETA;

    if (tid < 128) {
        ((float*)(smem + SM_COLSUM))[tid] = 0.f;
        ((float*)(smem + SM_COLSQ))[tid]  = 0.f;
        ((float*)(smem + SM_BIAS))[tid]   = gcn_b[layer * D + tid];
    }

    {
        const uint4* Bh = (const uint4*)(g_Bh + (size_t)layer * D * D);
#pragma unroll
        for (int i = 0; i < 8; i++) {
            int u = tid + i * 256;
            int n = u >> 4;
            int c = u & 15;
            *(uint4*)(smem + SM_WHI + sw_off(n, c)) = Bh[u];
        }
    }
    {
        const float4* A4 = (const float4*)buf;
#pragma unroll
        for (int i = 0; i < 16; i++) {
            int j = tid + i * 256;
            int m = j >> 5;
            int k4 = j & 31;
            int row = r0 + m;
            float4 x = (row < N_NODES) ? A4[(size_t)row * 32 + k4]
                                       : make_float4(0.f, 0.f, 0.f, 0.f);
            __nv_bfloat162 h01 = __float22bfloat162_rn(make_float2(x.x, x.y));
            __nv_bfloat162 h23 = __float22bfloat162_rn(make_float2(x.z, x.w));
            uint32_t off = sw_off(m, k4 >> 1) + (uint32_t)((k4 & 1) << 3);
            __nv_bfloat162* ph = (__nv_bfloat162*)(smem + SM_AHI + off);
            ph[0] = h01;
            ph[1] = h23;
        }
    }
    __syncthreads();

    int m0 = (wid & 3) * 32;
    int n0 = (wid >> 2) * 64;

    float acc[2][8][4];
#pragma unroll
    for (int mt = 0; mt < 2; mt++)
#pragma unroll
        for (int nt = 0; nt < 8; nt++)
#pragma unroll
            for (int q = 0; q < 4; q++) acc[mt][nt][q] = 0.f;

    int lr = lane & 7;
    int lm = lane >> 3;

#pragma unroll
    for (int kk = 0; kk < 8; kk++) {
        uint32_t ahi[2][4];
#pragma unroll
        for (int mt = 0; mt < 2; mt++) {
            int arow = m0 + mt * 16 + (lm & 1) * 8 + lr;
            int achk = kk * 2 + (lm >> 1);
            ldsm_x4(sb + SM_AHI + sw_off(arow, achk),
                    ahi[mt][0], ahi[mt][1], ahi[mt][2], ahi[mt][3]);
        }
        uint32_t bhi[8][2];
#pragma unroll
        for (int jp = 0; jp < 4; jp++) {
            int brow = n0 + jp * 16 + (lm >> 1) * 8 + lr;
            int bchk = kk * 2 + (lm & 1);
            ldsm_x4(sb + SM_WHI + sw_off(brow, bchk),
                    bhi[jp * 2][0], bhi[jp * 2][1], bhi[jp * 2 + 1][0], bhi[jp * 2 + 1][1]);
        }
#pragma unroll
        for (int mt = 0; mt < 2; mt++)
#pragma unroll
            for (int nt = 0; nt < 8; nt++)
                mma_bf16(acc[mt][nt], ahi[mt][0], ahi[mt][1], ahi[mt][2], ahi[mt][3],
                         bhi[nt][0], bhi[nt][1]);
    }

    float* bias = (float*)(smem + SM_BIAS);
    float* colsum = (float*)(smem + SM_COLSUM);
    float* colsq  = (float*)(smem + SM_COLSQ);
    int rl = lane >> 2;
    int cl = (lane & 3) * 2;

#pragma unroll
    for (int nt = 0; nt < 8; nt++) {
        int col = n0 + nt * 8 + cl;
        float b0v = bias[col], b1v = bias[col + 1];
        float s0 = 0.f, s1 = 0.f, q0 = 0.f, q1 = 0.f;
#pragma unroll
        for (int mt = 0; mt < 2; mt++) {
            int rlo = r0 + m0 + mt * 16 + rl;
            int rhi = rlo + 8;
            if (rlo < N_NODES) {
                float2 ga = *(const float2*)&buf[(size_t)rlo * D + col];
                float c0 = fmaf(BETA, acc[mt][nt][0], fmaf(OMB, ga.x, b0v));
                float c1 = fmaf(BETA, acc[mt][nt][1], fmaf(OMB, ga.y, b1v));
                *(float2*)&buf[(size_t)rlo * D + col] = make_float2(c0, c1);
                s0 += c0; s1 += c1;
                q0 = fmaf(c0, c0, q0); q1 = fmaf(c1, c1, q1);
            }
            if (rhi < N_NODES) {
                float2 ga = *(const float2*)&buf[(size_t)rhi * D + col];
                float c2 = fmaf(BETA, acc[mt][nt][2], fmaf(OMB, ga.x, b0v));
                float c3 = fmaf(BETA, acc[mt][nt][3], fmaf(OMB, ga.y, b1v));
                *(float2*)&buf[(size_t)rhi * D + col] = make_float2(c2, c3);
                s0 += c2; s1 += c3;
                q0 = fmaf(c2, c2, q0); q1 = fmaf(c3, c3, q1);
            }
        }
#pragma unroll
        for (int s = 4; s < 32; s <<= 1) {
            s0 += __shfl_xor_sync(0xffffffffu, s0, s);
            s1 += __shfl_xor_sync(0xffffffffu, s1, s);
            q0 += __shfl_xor_sync(0xffffffffu, q0, s);
            q1 += __shfl_xor_sync(0xffffffffu, q1, s);
        }
        if (lane < 4) {
            atomicAdd(&colsum[col], s0);
            atomicAdd(&colsum[col + 1], s1);
            atomicAdd(&colsq[col], q0);
            atomicAdd(&colsq[col + 1], q1);
        }
    }
    __syncthreads();
    if (tid < 128) {
        atomicAdd(&g_bn_sum[layer * D + tid], colsum[tid]);
        atomicAdd(&g_bn_sq[layer * D + tid], colsq[tid]);
    }
}

// ---------------- pool: branch-free segmented sum over graph ranges ----------------
// grid = N_GRAPHS * 2 blocks, 128 threads. Block (g, split) sums its half range.
__global__ void pool_kernel(int layer, const float* __restrict__ bn_g,
                            const float* __restrict__ bn_b) {
    int t = threadIdx.x;
    int g = blockIdx.x >> 1;
    int split = blockIdx.x & 1;
    const float* buf = (layer & 1) ? g_H : g_A;

    float inv_n = 1.0f / (float)N_NODES;
    float mu  = g_bn_sum[layer * D + t] * inv_n;
    float var = g_bn_sq[layer * D + t] * inv_n - mu * mu;
    float inv = rsqrtf(var + 1e-5f);
    float a = inv * bn_g[layer * D + t];
    float c = bn_b[layer * D + t] - mu * a;
    if (blockIdx.x == 0) {              // persist for next layer's spmm
        g_bn_a[layer * D + t] = a;
        g_bn_c[layer * D + t] = c;
    }

    int s = g_gstart[g], e = g_gstart[g + 1];
    int half = (e - s + 1) >> 1;
    int v0 = s + split * half;
    int v1 = min(v0 + half, e);
    float acc = 0.f;
#pragma unroll 4
    for (int v = v0; v < v1; v++)
        acc += fmaxf(fmaf(buf[(size_t)v * D + t], a, c), 0.f);
    atomicAdd(&g_pooled[(size_t)(layer + 1) * N_GRAPHS * D + (size_t)g * D + t], acc);
}

__global__ void pool_feat_kernel(const float* __restrict__ feat) {
    int t = threadIdx.x;
    int g = blockIdx.x >> 1;
    int split = blockIdx.x & 1;
    int s = g_gstart[g], e = g_gstart[g + 1];
    int half = (e - s + 1) >> 1;
    int v0 = s + split * half;
    int v1 = min(v0 + half, e);
    float acc = 0.f;
#pragma unroll 4
    for (int v = v0; v < v1; v++)
        acc += feat[(size_t)v * D + t];
    atomicAdd(&g_pooled[(size_t)g * D + t], acc);
}

// ---------------- head: score, log_softmax, mean_pooled ----------------
__global__ void head_kernel(const float* __restrict__ lin_w,
                            const float* __restrict__ lin_b,
                            float* __restrict__ out) {
    int g = blockIdx.x;
    int t = threadIdx.x;
    int lane = t & 31;
    __shared__ float red[OUTC];
    if (t < OUTC) red[t] = 0.f;
    __syncthreads();

    float p[NLAY + 1];
#pragma unroll
    for (int i = 0; i < NLAY + 1; i++)
        p[i] = g_pooled[(size_t)i * N_GRAPHS * D + (size_t)g * D + t];

    out[N_GRAPHS * OUTC + (size_t)g * D + t] =
        0.2f * (p[1] + p[2] + p[3] + p[4] + p[5]);

    float part[OUTC];
#pragma unroll
    for (int o = 0; o < OUTC; o++) part[o] = 0.f;
#pragma unroll
    for (int i = 0; i < NLAY + 1; i++) {
        const float* lw = lin_w + (size_t)i * D * OUTC + (size_t)t * OUTC;
#pragma unroll
        for (int o = 0; o < OUTC; o++) part[o] = fmaf(p[i], lw[o], part[o]);
    }
#pragma unroll
    for (int o = 0; o < OUTC; o++) {
        float v = part[o];
        for (int off = 16; off; off >>= 1) v += __shfl_down_sync(0xffffffffu, v, off);
        if (lane == 0) atomicAdd(&red[o], v);
    }
    __syncthreads();
    if (t == 0) {
        float s[OUTC];
        float mx = -1e30f;
        for (int o = 0; o < OUTC; o++) {
            float b = 0.f;
            for (int i = 0; i < NLAY + 1; i++) b += lin_b[i * OUTC + o];
            s[o] = red[o] + b;
            mx = fmaxf(mx, s[o]);
        }
        float lse = 0.f;
        for (int o = 0; o < OUTC; o++) lse += expf(s[o] - mx);
        lse = logf(lse) + mx;
        for (int o = 0; o < OUTC; o++) out[(size_t)g * OUTC + o] = s[o] - lse;
    }
}

// ---------------- launch ----------------
extern "C" void kernel_launch(void* const* d_in, const int* in_sizes, int n_in,
                              void* d_out, int out_size) {
    const float* feat     = (const float*)d_in[0];
    const int*   src      = (const int*)d_in[1];
    const int*   dst      = (const int*)d_in[2];
    const int*   graph_id = (const int*)d_in[3];
    const float* gcn_w    = (const float*)d_in[4];
    const float* gcn_b    = (const float*)d_in[5];
    const float* bn_g     = (const float*)d_in[6];
    const float* bn_b     = (const float*)d_in[7];
    const float* lin_w    = (const float*)d_in[8];
    const float* lin_b    = (const float*)d_in[9];
    float* out = (float*)d_out;

    cudaFuncSetAttribute(mma_gemm_kernel, cudaFuncAttributeMaxDynamicSharedMemorySize, SM_TOTAL);

    int spmm_blocks = (N_NODES * 32 + 255) / 256;
    int row_blocks  = (N_NODES + 127) / 128;

    degree_kernel<<<(N_EDGES + 255) / 256, 256>>>(src, dst);   // 1
    scan_kernel<<<SCAN_BLKS, 512>>>();                         // 2
    fill_kernel<<<(N_EDGES + 255) / 256, 256>>>(src, dst);     // 3
    spmm_kernel<<<spmm_blocks, 256>>>(0, feat);                // 4 <- profiled by ncu
    wcvt_kernel<<<256, 256>>>(gcn_w);                          // 5
    gcount_kernel<<<(N_NODES + 255) / 256, 256>>>(graph_id);   // 6
    gscan_kernel<<<1, 256>>>();                                // 7

    for (int l = 0; l < NLAY; l++) {
        if (l > 0) spmm_kernel<<<spmm_blocks, 256>>>(l, feat);
        mma_gemm_kernel<<<row_blocks, 256, SM_TOTAL>>>(l, gcn_b);
        pool_kernel<<<N_GRAPHS * 2, 128>>>(l, bn_g, bn_b);
    }
    pool_feat_kernel<<<N_GRAPHS * 2, 128>>>(feat);
    head_kernel<<<N_GRAPHS, 128>>>(lin_w, lin_b, out);
    tail_zero_kernel<<<512, 256>>>();
}